// round 4
// baseline (speedup 1.0000x reference)
#include <cuda_runtime.h>
#include <cuda_bf16.h>

#define NTOT (64*2048)
#define D    256
#define COND 64
#define HW   128
#define NG   64
#define NPG  2048
#define MSTRIDE 66

typedef unsigned long long u64;
typedef unsigned int u32;

// ---------------- device scratch ----------------
__device__ float g_pooled[NG*HW];
__device__ float g_u[NG*D];
__device__ float g_Gpart[128*COND*COND];
__device__ float g_spart[128*COND];
__device__ float g_G[COND*COND];
__device__ float g_s[NG*COND];
__device__ float g_a[D];
__device__ float g_c[D];
__device__ u64 g_Bfrag[8192];    // [term(2)][nt(32)][ks(4)][lane(32)] bf16 B fragments, 64 KB

extern __shared__ float dsm[];

// ---------------- helpers ----------------
__device__ __forceinline__ u64 fma2(u64 a, u64 b, u64 c){
    u64 d; asm("fma.rn.f32x2 %0, %1, %2, %3;" : "=l"(d) : "l"(a), "l"(b), "l"(c)); return d;
}
__device__ __forceinline__ unsigned short bf16hi_us(float w){
    return __bfloat16_as_ushort(__float2bfloat16(w));
}
__device__ __forceinline__ unsigned short bf16lo_us(float w){
    float r = w - __bfloat162float(__float2bfloat16(w));
    return __bfloat16_as_ushort(__float2bfloat16(r));
}
__device__ __forceinline__ void cvt_hl(float2 v, u32& hi, u32& lo){
    __nv_bfloat162 h = __float22bfloat162_rn(v);
    float2 hf = __bfloat1622float2(h);
    __nv_bfloat162 l2 = __float22bfloat162_rn(make_float2(v.x - hf.x, v.y - hf.y));
    hi = *reinterpret_cast<u32*>(&h);
    lo = *reinterpret_cast<u32*>(&l2);
}
__device__ __forceinline__ void mma16816(float* c, const u32* a, u32 b0, u32 b1){
    asm("mma.sync.aligned.m16n8k16.row.col.f32.bf16.bf16.f32 "
        "{%0,%1,%2,%3}, {%4,%5,%6,%7}, {%8,%9}, {%0,%1,%2,%3};"
        : "+f"(c[0]), "+f"(c[1]), "+f"(c[2]), "+f"(c[3])
        : "r"(a[0]), "r"(a[1]), "r"(a[2]), "r"(a[3]), "r"(b0), "r"(b1));
}

// ================= K0: prep (pool blocks 0..1023, Gram blocks 1024..1151) =================
__global__ void __launch_bounds__(256) prep_kernel(const float* __restrict__ x,
                                                   const float* __restrict__ cond){
    int tid = threadIdx.x;
    int blk = blockIdx.x;
    if (blk < 1024){
        int b = blk >> 4, oh = blk & 15;
        const float* p = x + ((size_t)(b*NPG + oh*128))*D + tid;
        float s = 0.0f;
        #pragma unroll 8
        for (int r = 0; r < 128; r++) s += p[(size_t)r*D];
        #pragma unroll
        for (int o = 16; o > 0; o >>= 1) s += __shfl_down_sync(0xffffffffu, s, o);
        if ((tid & 31) == 0) g_pooled[b*HW + oh*8 + (tid >> 5)] = s * (1.0f/4096.0f);
        return;
    }
    int gb = blk - 1024;                      // 0..127 : 1024 rows each
    float*  tile = dsm;                       // [128][64]
    float2* adup = (float2*)(dsm + 8192);     // [128][64] duplicated
    int ti = tid >> 4, tj = tid & 15;
    int ri = ti*4, cj = tj*4;
    u64 acc[4][2];
    #pragma unroll
    for (int r = 0; r < 4; r++){ acc[r][0] = 0ull; acc[r][1] = 0ull; }
    float ssum = 0.0f;

    for (int sub = 0; sub < 8; sub++){
        size_t base = ((size_t)gb*1024 + sub*128) * COND;
        for (int i = tid; i < 8192; i += 256){
            float v = cond[base + i];
            tile[i] = v;
            adup[i] = make_float2(v, v);
        }
        __syncthreads();
        #pragma unroll 4
        for (int k = 0; k < 128; k++){
            ulonglong2 a01 = *(const ulonglong2*)(adup + k*64 + ri);
            ulonglong2 a23 = *(const ulonglong2*)(adup + k*64 + ri + 2);
            ulonglong2 bb  = *(const ulonglong2*)(tile + k*64 + cj);
            acc[0][0] = fma2(a01.x, bb.x, acc[0][0]);
            acc[0][1] = fma2(a01.x, bb.y, acc[0][1]);
            acc[1][0] = fma2(a01.y, bb.x, acc[1][0]);
            acc[1][1] = fma2(a01.y, bb.y, acc[1][1]);
            acc[2][0] = fma2(a23.x, bb.x, acc[2][0]);
            acc[2][1] = fma2(a23.x, bb.y, acc[2][1]);
            acc[3][0] = fma2(a23.y, bb.x, acc[3][0]);
            acc[3][1] = fma2(a23.y, bb.y, acc[3][1]);
        }
        if (tid < 64){
            #pragma unroll 8
            for (int k = 0; k < 128; k++) ssum += tile[k*64 + tid];
        }
        __syncthreads();
    }
    u64* gp = (u64*)(g_Gpart + (size_t)gb*4096);
    #pragma unroll
    for (int r = 0; r < 4; r++){
        gp[((ri + r)*64 + cj)/2    ] = acc[r][0];
        gp[((ri + r)*64 + cj)/2 + 1] = acc[r][1];
    }
    if (tid < 64) g_spart[gb*64 + tid] = ssum;
}

// ================= K1: reduce Gram/s + build bf16 B fragment images =================
__global__ void __launch_bounds__(256) reduce_kernel(const float* __restrict__ W1){
    int blk = blockIdx.x, tid = threadIdx.x;
    if (blk < 8){
        for (int it = 0; it < 2; it++){
            int e = blk*512 + it*256 + tid;
            float s = 0.0f;
            #pragma unroll 4
            for (int p = 0; p < 128; p++) s += g_Gpart[p*4096 + e];
            g_G[e] = s;
        }
    } else if (blk == 8){
        for (int e = tid; e < NG*COND; e += 256){
            int g = e >> 6, k = e & 63;
            g_s[e] = g_spart[(2*g)*64 + k] + g_spart[(2*g+1)*64 + k];
        }
    } else {
        // blocks 9..16: build g_Bfrag  [term][nt][ks][lane]
        int base = (blk - 9)*256 + tid;
        for (int e = base; e < 8192; e += 2048){
            int lane = e & 31, ks = (e >> 5) & 3, nt = (e >> 7) & 31, term = e >> 12;
            int k0 = 16*ks + 2*(lane & 3);
            int n  = nt*8 + (lane >> 2);
            float w0 = W1[(k0    )*D + n];
            float w1 = W1[(k0 + 1)*D + n];
            float w8 = W1[(k0 + 8)*D + n];
            float w9 = W1[(k0 + 9)*D + n];
            unsigned short p0, p1, p8, p9;
            if (term == 0){
                p0 = bf16hi_us(w0); p1 = bf16hi_us(w1);
                p8 = bf16hi_us(w8); p9 = bf16hi_us(w9);
            } else {
                p0 = bf16lo_us(w0); p1 = bf16lo_us(w1);
                p8 = bf16lo_us(w8); p9 = bf16lo_us(w9);
            }
            u32 lo32 = (u32)p0 | ((u32)p1 << 16);
            u32 hi32 = (u32)p8 | ((u32)p9 << 16);
            g_Bfrag[e] = (u64)lo32 | ((u64)hi32 << 32);
        }
    }
}

// ================= K2: stats — u[g][j], BN affine a,c (analytic) =================
__global__ void __launch_bounds__(256) stats_kernel(const float* __restrict__ W1,
                                                    const float* __restrict__ b1,
                                                    const float* __restrict__ gamma,
                                                    const float* __restrict__ beta){
    __shared__ float wcol[4][64];
    __shared__ float wb[4][128];
    __shared__ float red1[256], red2[256], red3[256];
    int tid = threadIdx.x;
    int jj = tid >> 6, s = tid & 63;
    int j = blockIdx.x*4 + jj;

    wcol[jj][s]   = W1[s*D + j];
    wb[jj][s]     = W1[(64 + s)*D + j];
    wb[jj][64+s]  = W1[(128 + s)*D + j];
    __syncthreads();

    float t = 0.0f;
    #pragma unroll 8
    for (int m = 0; m < 64; m++) t += g_G[s*64 + m] * wcol[jj][m];
    float wGw_part = wcol[jj][s] * t;

    float u = b1[j];
    #pragma unroll 8
    for (int k = 0; k < 128; k++) u += g_pooled[s*128 + k] * wb[jj][k];
    g_u[s*D + j] = u;
    float sgw = 0.0f;
    #pragma unroll 8
    for (int k = 0; k < 64; k++) sgw += g_s[s*64 + k] * wcol[jj][k];

    red1[tid] = sgw + 2048.0f*u;
    red2[tid] = 2.0f*u*sgw + 2048.0f*u*u;
    red3[tid] = wGw_part;
    __syncthreads();
    for (int o = 32; o > 0; o >>= 1){
        if (s < o){
            red1[tid] += red1[tid + o];
            red2[tid] += red2[tid + o];
            red3[tid] += red3[tid + o];
        }
        __syncthreads();
    }
    if (s == 0){
        const float invN = 1.0f / (float)NTOT;
        float mean  = red1[jj*64] * invN;
        float sumsq = red3[jj*64] + red2[jj*64];
        float var   = sumsq * invN - mean*mean;
        float a = gamma[j] * rsqrtf(var + 1e-5f);
        g_a[j] = a;
        g_c[j] = beta[j] - mean*a;
    }
}

// ================= K3: fused main — mma.sync split-bf16 GEMM + BN + GELU + GEMV =================
__global__ void __launch_bounds__(256) main_kernel(const float* __restrict__ cond,
                                                   const float* __restrict__ W2,
                                                   const float* __restrict__ b2,
                                                   float* __restrict__ out){
    u64*   sB  = (u64*)dsm;                    // 8192 u64 = 64 KB
    float* sA  = dsm + 16384;                  // 64 x MSTRIDE floats
    float* sa  = sA + 64*MSTRIDE;              // 256
    float* sfc = sa + 256;                     // 256
    float* sw2 = sfc + 256;                    // 768
    __shared__ float sred[8][16][3];

    int tid = threadIdx.x, wid = tid >> 5, l = tid & 31;
    int row0 = blockIdx.x * 64;
    int g = blockIdx.x >> 5;                   // 32 blocks per graph

    // stage B fragments (64 KB)
    {
        const uint4* src = (const uint4*)g_Bfrag;
        uint4* dst = (uint4*)sB;
        #pragma unroll
        for (int i = tid; i < 4096; i += 256) dst[i] = src[i];
    }
    // stage A tile (64 rows x 64 f32, padded stride)
    for (int i = tid; i < 1024; i += 256){
        int r = i >> 4, c4 = (i & 15) * 4;
        float4 v = *(const float4*)(cond + (size_t)(row0 + r)*COND + c4);
        float* d = sA + r*MSTRIDE + c4;
        ((float2*)d)[0] = make_float2(v.x, v.y);
        ((float2*)d)[1] = make_float2(v.z, v.w);
    }
    // coefficients (fold per-graph bias u into the BN offset)
    {
        float a = g_a[tid];
        sa[tid]  = a;
        sfc[tid] = fmaf(g_u[g*D + tid], a, g_c[tid]);
    }
    for (int i = tid; i < 768; i += 256) sw2[i] = W2[i];
    __syncthreads();

    int rbase = (wid >> 1) * 16;               // 4 row groups of 16
    int nth   = (wid & 1);                     // column half (128 cols)

    float acc[16][4];
    #pragma unroll
    for (int nt = 0; nt < 16; nt++)
        #pragma unroll
        for (int q = 0; q < 4; q++) acc[nt][q] = 0.0f;

    #pragma unroll
    for (int ks = 0; ks < 4; ks++){
        int c0 = 16*ks + 2*(l & 3);
        int r  = rbase + (l >> 2);
        float2 v00 = *(const float2*)(sA + r*MSTRIDE + c0);
        float2 v10 = *(const float2*)(sA + (r+8)*MSTRIDE + c0);
        float2 v01 = *(const float2*)(sA + r*MSTRIDE + c0 + 8);
        float2 v11 = *(const float2*)(sA + (r+8)*MSTRIDE + c0 + 8);
        u32 ah[4], al[4];
        cvt_hl(v00, ah[0], al[0]);
        cvt_hl(v10, ah[1], al[1]);
        cvt_hl(v01, ah[2], al[2]);
        cvt_hl(v11, ah[3], al[3]);
        #pragma unroll
        for (int nt = 0; nt < 16; nt++){
            int ntg = nth*16 + nt;
            u64 bh = sB[(      ntg*4 + ks)*32 + l];
            u64 bl = sB[((32 + ntg)*4 + ks)*32 + l];
            u32 bh0 = (u32)bh, bh1 = (u32)(bh >> 32);
            u32 bl0 = (u32)bl, bl1 = (u32)(bl >> 32);
            mma16816(acc[nt], ah, bh0, bh1);
            mma16816(acc[nt], ah, bl0, bl1);
            mma16816(acc[nt], al, bh0, bh1);
        }
    }

    // epilogue: BN + exact GELU + 3-col GEMV partials
    float o0[3] = {0,0,0}, o1[3] = {0,0,0};
    #pragma unroll
    for (int nt = 0; nt < 16; nt++){
        int col = (nth*16 + nt)*8 + 2*(l & 3);
        #pragma unroll
        for (int q = 0; q < 4; q++){
            int c = col + (q & 1);
            float v = acc[nt][q];
            float y = fmaf(v, sa[c], sfc[c]);
            float gl = 0.5f * y * (1.0f + erff(y * 0.70710678118654752f));
            float* o = (q < 2) ? o0 : o1;
            o[0] = fmaf(gl, sw2[c*3 + 0], o[0]);
            o[1] = fmaf(gl, sw2[c*3 + 1], o[1]);
            o[2] = fmaf(gl, sw2[c*3 + 2], o[2]);
        }
    }
    #pragma unroll
    for (int j = 0; j < 3; j++){
        o0[j] += __shfl_xor_sync(0xffffffffu, o0[j], 1);
        o0[j] += __shfl_xor_sync(0xffffffffu, o0[j], 2);
        o1[j] += __shfl_xor_sync(0xffffffffu, o1[j], 1);
        o1[j] += __shfl_xor_sync(0xffffffffu, o1[j], 2);
    }
    if ((l & 3) == 0){
        int rl = l >> 2;
        #pragma unroll
        for (int j = 0; j < 3; j++){
            sred[wid][rl][j]     = o0[j];
            sred[wid][rl + 8][j] = o1[j];
        }
    }
    __syncthreads();
    if (tid < 192){
        int rg = tid / 48, rem = tid % 48, row = rem / 3, j = rem % 3;
        out[((size_t)row0 + rg*16 + row)*3 + j] =
            sred[2*rg][row][j] + sred[2*rg + 1][row][j] + b2[j];
    }
}

// ================= launch =================
extern "C" void kernel_launch(void* const* d_in, const int* in_sizes, int n_in,
                              void* d_out, int out_size){
    const float* x     = (const float*)d_in[0];
    const float* cond  = (const float*)d_in[2];
    const float* W1    = (const float*)d_in[3];
    const float* b1    = (const float*)d_in[4];
    const float* gamma = (const float*)d_in[5];
    const float* beta  = (const float*)d_in[6];
    const float* W2    = (const float*)d_in[7];
    const float* b2    = (const float*)d_in[8];
    float* out = (float*)d_out;

    static int configured = 0;
    if (!configured){
        cudaFuncSetAttribute(prep_kernel, cudaFuncAttributeMaxDynamicSharedMemorySize, 98304);
        cudaFuncSetAttribute(main_kernel, cudaFuncAttributeMaxDynamicSharedMemorySize, 92160);
        configured = 1;
    }

    prep_kernel  <<<1152, 256, 98304>>>(x, cond);
    reduce_kernel<<<17,   256>>>(W1);
    stats_kernel <<<64,   256>>>(W1, b1, gamma, beta);
    // dyn smem: 64KB B + 64*66*4 A + (256+256+768)*4 = 87552
    main_kernel  <<<2048, 256, 87552>>>(cond, W2, b2, out);
}

// round 5
// speedup vs baseline: 1.1533x; 1.1533x over previous
#include <cuda_runtime.h>
#include <cuda_bf16.h>

#define NTOT (64*2048)
#define D    256
#define COND 64
#define HW   128
#define NG   64
#define NPG  2048
#define MSTRIDE 66

typedef unsigned long long u64;
typedef unsigned int u32;

// ---------------- device scratch ----------------
__device__ float g_pooled[NG*HW];
__device__ float g_u[NG*D];
__device__ float g_Gpart[128*COND*COND];
__device__ float g_spart[128*COND];
__device__ float g_G[COND*COND];
__device__ float g_s[NG*COND];
__device__ float g_a[D];
__device__ float g_c[D];
__device__ u64 g_Bfrag[8192];    // [nt(32)][ks(4)][lane(32)]{hi,lo} bf16 B fragments, 64 KB

extern __shared__ float dsm[];

// ---------------- helpers ----------------
__device__ __forceinline__ u64 fma2(u64 a, u64 b, u64 c){
    u64 d; asm("fma.rn.f32x2 %0, %1, %2, %3;" : "=l"(d) : "l"(a), "l"(b), "l"(c)); return d;
}
__device__ __forceinline__ unsigned short bf16hi_us(float w){
    return __bfloat16_as_ushort(__float2bfloat16(w));
}
__device__ __forceinline__ unsigned short bf16lo_us(float w){
    float r = w - __bfloat162float(__float2bfloat16(w));
    return __bfloat16_as_ushort(__float2bfloat16(r));
}
__device__ __forceinline__ void cvt_hl(float2 v, u32& hi, u32& lo){
    __nv_bfloat162 h = __float22bfloat162_rn(v);
    float2 hf = __bfloat1622float2(h);
    __nv_bfloat162 l2 = __float22bfloat162_rn(make_float2(v.x - hf.x, v.y - hf.y));
    hi = *reinterpret_cast<u32*>(&h);
    lo = *reinterpret_cast<u32*>(&l2);
}
__device__ __forceinline__ void mma16816(float* c, const u32* a, u32 b0, u32 b1){
    asm("mma.sync.aligned.m16n8k16.row.col.f32.bf16.bf16.f32 "
        "{%0,%1,%2,%3}, {%4,%5,%6,%7}, {%8,%9}, {%0,%1,%2,%3};"
        : "+f"(c[0]), "+f"(c[1]), "+f"(c[2]), "+f"(c[3])
        : "r"(a[0]), "r"(a[1]), "r"(a[2]), "r"(a[3]), "r"(b0), "r"(b1));
}

// ================= K0a: pool (no dyn smem -> full occupancy, HBM-bound) =================
__global__ void __launch_bounds__(256) pool_kernel(const float* __restrict__ x){
    int blk = blockIdx.x;
    int b = blk >> 4, oh = blk & 15;
    int tid = threadIdx.x;
    const float* p = x + ((size_t)(b*NPG + oh*128))*D + tid;
    float s = 0.0f;
    #pragma unroll 16
    for (int r = 0; r < 128; r++) s += p[(size_t)r*D];
    #pragma unroll
    for (int o = 16; o > 0; o >>= 1) s += __shfl_down_sync(0xffffffffu, s, o);
    if ((tid & 31) == 0) g_pooled[b*HW + oh*8 + (tid >> 5)] = s * (1.0f/4096.0f);
}

// ================= K0b: Gram partials (96 KB smem, own launch) =================
__global__ void __launch_bounds__(256) gram_kernel(const float* __restrict__ cond){
    int tid = threadIdx.x;
    int gb = blockIdx.x;                      // 0..127 : 1024 rows each
    float*  tile = dsm;                       // [128][64]
    float2* adup = (float2*)(dsm + 8192);     // [128][64] duplicated
    int ti = tid >> 4, tj = tid & 15;
    int ri = ti*4, cj = tj*4;
    u64 acc[4][2];
    #pragma unroll
    for (int r = 0; r < 4; r++){ acc[r][0] = 0ull; acc[r][1] = 0ull; }
    float ssum = 0.0f;

    for (int sub = 0; sub < 8; sub++){
        size_t base = ((size_t)gb*1024 + sub*128) * COND;
        for (int i = tid; i < 8192; i += 256){
            float v = cond[base + i];
            tile[i] = v;
            adup[i] = make_float2(v, v);
        }
        __syncthreads();
        #pragma unroll 4
        for (int k = 0; k < 128; k++){
            ulonglong2 a01 = *(const ulonglong2*)(adup + k*64 + ri);
            ulonglong2 a23 = *(const ulonglong2*)(adup + k*64 + ri + 2);
            ulonglong2 bb  = *(const ulonglong2*)(tile + k*64 + cj);
            acc[0][0] = fma2(a01.x, bb.x, acc[0][0]);
            acc[0][1] = fma2(a01.x, bb.y, acc[0][1]);
            acc[1][0] = fma2(a01.y, bb.x, acc[1][0]);
            acc[1][1] = fma2(a01.y, bb.y, acc[1][1]);
            acc[2][0] = fma2(a23.x, bb.x, acc[2][0]);
            acc[2][1] = fma2(a23.x, bb.y, acc[2][1]);
            acc[3][0] = fma2(a23.y, bb.x, acc[3][0]);
            acc[3][1] = fma2(a23.y, bb.y, acc[3][1]);
        }
        if (tid < 64){
            #pragma unroll 8
            for (int k = 0; k < 128; k++) ssum += tile[k*64 + tid];
        }
        __syncthreads();
    }
    u64* gp = (u64*)(g_Gpart + (size_t)gb*4096);
    #pragma unroll
    for (int r = 0; r < 4; r++){
        gp[((ri + r)*64 + cj)/2    ] = acc[r][0];
        gp[((ri + r)*64 + cj)/2 + 1] = acc[r][1];
    }
    if (tid < 64) g_spart[gb*64 + tid] = ssum;
}

// ================= K1: reduce Gram/s + build bf16 B fragment images =================
__global__ void __launch_bounds__(256) reduce_kernel(const float* __restrict__ W1){
    int blk = blockIdx.x, tid = threadIdx.x;
    if (blk < 8){
        for (int it = 0; it < 2; it++){
            int e = blk*512 + it*256 + tid;
            float s = 0.0f;
            #pragma unroll 4
            for (int p = 0; p < 128; p++) s += g_Gpart[p*4096 + e];
            g_G[e] = s;
        }
    } else if (blk == 8){
        for (int e = tid; e < NG*COND; e += 256){
            int g = e >> 6, k = e & 63;
            g_s[e] = g_spart[(2*g)*64 + k] + g_spart[(2*g+1)*64 + k];
        }
    } else {
        // blocks 9..16: build g_Bfrag  [nt][ks][lane]{hi,lo}
        int base = (blk - 9)*256 + tid;       // 0..2047
        for (int s = base; s < 4096; s += 2048){
            int lane = s & 31, ks = (s >> 5) & 3, nt = s >> 7;
            int k0 = 16*ks + 2*(lane & 3);
            int n  = nt*8 + (lane >> 2);
            float w0 = W1[(k0    )*D + n];
            float w1 = W1[(k0 + 1)*D + n];
            float w8 = W1[(k0 + 8)*D + n];
            float w9 = W1[(k0 + 9)*D + n];
            u32 h0 = (u32)bf16hi_us(w0) | ((u32)bf16hi_us(w1) << 16);
            u32 h1 = (u32)bf16hi_us(w8) | ((u32)bf16hi_us(w9) << 16);
            u32 l0 = (u32)bf16lo_us(w0) | ((u32)bf16lo_us(w1) << 16);
            u32 l1 = (u32)bf16lo_us(w8) | ((u32)bf16lo_us(w9) << 16);
            g_Bfrag[2*s    ] = (u64)h0 | ((u64)h1 << 32);
            g_Bfrag[2*s + 1] = (u64)l0 | ((u64)l1 << 32);
        }
    }
}

// ================= K2: stats — u[g][j], BN affine a,c (analytic) =================
__global__ void __launch_bounds__(256) stats_kernel(const float* __restrict__ W1,
                                                    const float* __restrict__ b1,
                                                    const float* __restrict__ gamma,
                                                    const float* __restrict__ beta){
    __shared__ float wcol[4][64];
    __shared__ float wb[4][128];
    __shared__ float red1[256], red2[256], red3[256];
    int tid = threadIdx.x;
    int jj = tid >> 6, s = tid & 63;
    int j = blockIdx.x*4 + jj;

    wcol[jj][s]   = W1[s*D + j];
    wb[jj][s]     = W1[(64 + s)*D + j];
    wb[jj][64+s]  = W1[(128 + s)*D + j];
    __syncthreads();

    float t = 0.0f;
    #pragma unroll 8
    for (int m = 0; m < 64; m++) t += g_G[s*64 + m] * wcol[jj][m];
    float wGw_part = wcol[jj][s] * t;

    float u = b1[j];
    #pragma unroll 8
    for (int k = 0; k < 128; k++) u += g_pooled[s*128 + k] * wb[jj][k];
    g_u[s*D + j] = u;
    float sgw = 0.0f;
    #pragma unroll 8
    for (int k = 0; k < 64; k++) sgw += g_s[s*64 + k] * wcol[jj][k];

    red1[tid] = sgw + 2048.0f*u;
    red2[tid] = 2.0f*u*sgw + 2048.0f*u*u;
    red3[tid] = wGw_part;
    __syncthreads();
    for (int o = 32; o > 0; o >>= 1){
        if (s < o){
            red1[tid] += red1[tid + o];
            red2[tid] += red2[tid + o];
            red3[tid] += red3[tid + o];
        }
        __syncthreads();
    }
    if (s == 0){
        const float invN = 1.0f / (float)NTOT;
        float mean  = red1[jj*64] * invN;
        float sumsq = red3[jj*64] + red2[jj*64];
        float var   = sumsq * invN - mean*mean;
        float a = gamma[j] * rsqrtf(var + 1e-5f);
        g_a[j] = a;
        g_c[j] = beta[j] - mean*a;
    }
}

// ================= K3: fused main — mma.sync split-bf16 GEMM + BN + GELU + GEMV =================
__global__ void __launch_bounds__(256) main_kernel(const float* __restrict__ cond,
                                                   const float* __restrict__ W2,
                                                   const float* __restrict__ b2,
                                                   float* __restrict__ out){
    u64*   sB  = (u64*)dsm;                    // 8192 u64 = 64 KB
    float* sA  = dsm + 16384;                  // 64 x MSTRIDE floats
    float* sa  = sA + 64*MSTRIDE;              // 256
    float* sfc = sa + 256;                     // 256
    float* sw2 = sfc + 256;                    // 768
    __shared__ float sred[8][16][3];

    int tid = threadIdx.x, wid = tid >> 5, l = tid & 31;
    int row0 = blockIdx.x * 64;
    int g = blockIdx.x >> 5;                   // 32 blocks per graph

    // stage B fragments (64 KB)
    {
        const uint4* src = (const uint4*)g_Bfrag;
        uint4* dst = (uint4*)sB;
        #pragma unroll
        for (int i = tid; i < 4096; i += 256) dst[i] = src[i];
    }
    // stage A tile (64 rows x 64 f32, padded stride)
    for (int i = tid; i < 1024; i += 256){
        int r = i >> 4, c4 = (i & 15) * 4;
        float4 v = *(const float4*)(cond + (size_t)(row0 + r)*COND + c4);
        float* d = sA + r*MSTRIDE + c4;
        ((float2*)d)[0] = make_float2(v.x, v.y);
        ((float2*)d)[1] = make_float2(v.z, v.w);
    }
    // coefficients (fold per-graph bias u into the BN offset)
    {
        float a = g_a[tid];
        sa[tid]  = a;
        sfc[tid] = fmaf(g_u[g*D + tid], a, g_c[tid]);
    }
    for (int i = tid; i < 768; i += 256) sw2[i] = W2[i];
    __syncthreads();

    int rbase = (wid >> 1) * 16;               // 4 row groups of 16
    int nth   = (wid & 1);                     // column half (128 cols)

    float acc[16][4];
    #pragma unroll
    for (int nt = 0; nt < 16; nt++)
        #pragma unroll
        for (int q = 0; q < 4; q++) acc[nt][q] = 0.0f;

    const uint4* sB4 = (const uint4*)sB;
    #pragma unroll
    for (int ks = 0; ks < 4; ks++){
        int c0 = 16*ks + 2*(l & 3);
        int r  = rbase + (l >> 2);
        float2 v00 = *(const float2*)(sA + r*MSTRIDE + c0);
        float2 v10 = *(const float2*)(sA + (r+8)*MSTRIDE + c0);
        float2 v01 = *(const float2*)(sA + r*MSTRIDE + c0 + 8);
        float2 v11 = *(const float2*)(sA + (r+8)*MSTRIDE + c0 + 8);
        u32 ah[4], al[4];
        cvt_hl(v00, ah[0], al[0]);
        cvt_hl(v10, ah[1], al[1]);
        cvt_hl(v01, ah[2], al[2]);
        cvt_hl(v11, ah[3], al[3]);
        const uint4* bp = sB4 + (nth*16*4 + ks)*32 + l;
        #pragma unroll
        for (int nt = 0; nt < 16; nt++){
            uint4 b = bp[nt*128];              // {bh0,bh1,bl0,bl1}
            mma16816(acc[nt], ah, b.x, b.y);
            mma16816(acc[nt], ah, b.z, b.w);
            mma16816(acc[nt], al, b.x, b.y);
        }
    }

    // epilogue: BN + exact GELU + 3-col GEMV partials
    float o0[3] = {0,0,0}, o1[3] = {0,0,0};
    #pragma unroll
    for (int nt = 0; nt < 16; nt++){
        int col = (nth*16 + nt)*8 + 2*(l & 3);
        #pragma unroll
        for (int q = 0; q < 4; q++){
            int c = col + (q & 1);
            float v = acc[nt][q];
            float y = fmaf(v, sa[c], sfc[c]);
            float gl = 0.5f * y * (1.0f + erff(y * 0.70710678118654752f));
            float* o = (q < 2) ? o0 : o1;
            o[0] = fmaf(gl, sw2[c*3 + 0], o[0]);
            o[1] = fmaf(gl, sw2[c*3 + 1], o[1]);
            o[2] = fmaf(gl, sw2[c*3 + 2], o[2]);
        }
    }
    #pragma unroll
    for (int j = 0; j < 3; j++){
        o0[j] += __shfl_xor_sync(0xffffffffu, o0[j], 1);
        o0[j] += __shfl_xor_sync(0xffffffffu, o0[j], 2);
        o1[j] += __shfl_xor_sync(0xffffffffu, o1[j], 1);
        o1[j] += __shfl_xor_sync(0xffffffffu, o1[j], 2);
    }
    if ((l & 3) == 0){
        int rl = l >> 2;
        #pragma unroll
        for (int j = 0; j < 3; j++){
            sred[wid][rl][j]     = o0[j];
            sred[wid][rl + 8][j] = o1[j];
        }
    }
    __syncthreads();
    if (tid < 192){
        int rg = tid / 48, rem = tid % 48, row = rem / 3, j = rem % 3;
        out[((size_t)row0 + rg*16 + row)*3 + j] =
            sred[2*rg][row][j] + sred[2*rg + 1][row][j] + b2[j];
    }
}

// ================= launch =================
extern "C" void kernel_launch(void* const* d_in, const int* in_sizes, int n_in,
                              void* d_out, int out_size){
    const float* x     = (const float*)d_in[0];
    const float* cond  = (const float*)d_in[2];
    const float* W1    = (const float*)d_in[3];
    const float* b1    = (const float*)d_in[4];
    const float* gamma = (const float*)d_in[5];
    const float* beta  = (const float*)d_in[6];
    const float* W2    = (const float*)d_in[7];
    const float* b2    = (const float*)d_in[8];
    float* out = (float*)d_out;

    static int configured = 0;
    if (!configured){
        cudaFuncSetAttribute(gram_kernel, cudaFuncAttributeMaxDynamicSharedMemorySize, 98304);
        cudaFuncSetAttribute(main_kernel, cudaFuncAttributeMaxDynamicSharedMemorySize, 92160);
        configured = 1;
    }

    gram_kernel  <<<128,  256, 98304>>>(cond);
    pool_kernel  <<<1024, 256>>>(x);
    reduce_kernel<<<17,   256>>>(W1);
    stats_kernel <<<64,   256>>>(W1, b1, gamma, beta);
    main_kernel  <<<2048, 256, 87552>>>(cond, W2, b2, out);
}

// round 6
// speedup vs baseline: 1.1701x; 1.0146x over previous
#include <cuda_runtime.h>
#include <cuda_bf16.h>

#define NTOT (64*2048)
#define D    256
#define COND 64
#define HW   128
#define NG   64
#define NPG  2048
#define MSTRIDE 66

typedef unsigned long long u64;
typedef unsigned int u32;

// ---------------- device scratch ----------------
__device__ float g_pooled[NG*HW];
__device__ float g_u[NG*D];
__device__ float g_Gpart[128*COND*COND];
__device__ float g_spart[128*COND];
__device__ float g_G[COND*COND];
__device__ float g_s[NG*COND];
__device__ float g_a[D];
__device__ float g_c[D];
__device__ u64 g_Bfrag[8192];    // [nt(32)][ks(4)][lane(32)]{hi,lo} bf16 B fragments, 64 KB

extern __shared__ float dsm[];

// ---------------- helpers ----------------
__device__ __forceinline__ u64 fma2(u64 a, u64 b, u64 c){
    u64 d; asm("fma.rn.f32x2 %0, %1, %2, %3;" : "=l"(d) : "l"(a), "l"(b), "l"(c)); return d;
}
__device__ __forceinline__ unsigned short bf16hi_us(float w){
    return __bfloat16_as_ushort(__float2bfloat16(w));
}
__device__ __forceinline__ unsigned short bf16lo_us(float w){
    float r = w - __bfloat162float(__float2bfloat16(w));
    return __bfloat16_as_ushort(__float2bfloat16(r));
}
__device__ __forceinline__ void cvt_hl(float2 v, u32& hi, u32& lo){
    __nv_bfloat162 h = __float22bfloat162_rn(v);
    float2 hf = __bfloat1622float2(h);
    __nv_bfloat162 l2 = __float22bfloat162_rn(make_float2(v.x - hf.x, v.y - hf.y));
    hi = *reinterpret_cast<u32*>(&h);
    lo = *reinterpret_cast<u32*>(&l2);
}
__device__ __forceinline__ void mma16816(float* c, const u32* a, u32 b0, u32 b1){
    asm("mma.sync.aligned.m16n8k16.row.col.f32.bf16.bf16.f32 "
        "{%0,%1,%2,%3}, {%4,%5,%6,%7}, {%8,%9}, {%0,%1,%2,%3};"
        : "+f"(c[0]), "+f"(c[1]), "+f"(c[2]), "+f"(c[3])
        : "r"(a[0]), "r"(a[1]), "r"(a[2]), "r"(a[3]), "r"(b0), "r"(b1));
}

// ================= K0a: pool (no dyn smem -> full occupancy, HBM-bound) =================
__global__ void __launch_bounds__(256) pool_kernel(const float* __restrict__ x){
    int blk = blockIdx.x;
    int b = blk >> 4, oh = blk & 15;
    int tid = threadIdx.x;
    const float* p = x + ((size_t)(b*NPG + oh*128))*D + tid;
    float s = 0.0f;
    #pragma unroll 16
    for (int r = 0; r < 128; r++) s += p[(size_t)r*D];
    #pragma unroll
    for (int o = 16; o > 0; o >>= 1) s += __shfl_down_sync(0xffffffffu, s, o);
    if ((tid & 31) == 0) g_pooled[b*HW + oh*8 + (tid >> 5)] = s * (1.0f/4096.0f);
}

// ================= K0b: Gram partials (96 KB smem, own launch) =================
__global__ void __launch_bounds__(256) gram_kernel(const float* __restrict__ cond){
    int tid = threadIdx.x;
    int gb = blockIdx.x;                      // 0..127 : 1024 rows each
    float*  tile = dsm;                       // [128][64]
    float2* adup = (float2*)(dsm + 8192);     // [128][64] duplicated
    int ti = tid >> 4, tj = tid & 15;
    int ri = ti*4, cj = tj*4;
    u64 acc[4][2];
    #pragma unroll
    for (int r = 0; r < 4; r++){ acc[r][0] = 0ull; acc[r][1] = 0ull; }
    float ssum = 0.0f;

    for (int sub = 0; sub < 8; sub++){
        size_t base = ((size_t)gb*1024 + sub*128) * COND;
        for (int i = tid; i < 8192; i += 256){
            float v = cond[base + i];
            tile[i] = v;
            adup[i] = make_float2(v, v);
        }
        __syncthreads();
        #pragma unroll 4
        for (int k = 0; k < 128; k++){
            ulonglong2 a01 = *(const ulonglong2*)(adup + k*64 + ri);
            ulonglong2 a23 = *(const ulonglong2*)(adup + k*64 + ri + 2);
            ulonglong2 bb  = *(const ulonglong2*)(tile + k*64 + cj);
            acc[0][0] = fma2(a01.x, bb.x, acc[0][0]);
            acc[0][1] = fma2(a01.x, bb.y, acc[0][1]);
            acc[1][0] = fma2(a01.y, bb.x, acc[1][0]);
            acc[1][1] = fma2(a01.y, bb.y, acc[1][1]);
            acc[2][0] = fma2(a23.x, bb.x, acc[2][0]);
            acc[2][1] = fma2(a23.x, bb.y, acc[2][1]);
            acc[3][0] = fma2(a23.y, bb.x, acc[3][0]);
            acc[3][1] = fma2(a23.y, bb.y, acc[3][1]);
        }
        if (tid < 64){
            #pragma unroll 8
            for (int k = 0; k < 128; k++) ssum += tile[k*64 + tid];
        }
        __syncthreads();
    }
    u64* gp = (u64*)(g_Gpart + (size_t)gb*4096);
    #pragma unroll
    for (int r = 0; r < 4; r++){
        gp[((ri + r)*64 + cj)/2    ] = acc[r][0];
        gp[((ri + r)*64 + cj)/2 + 1] = acc[r][1];
    }
    if (tid < 64) g_spart[gb*64 + tid] = ssum;
}

// ================= K1: reduce Gram/s + build bf16 B fragment images =================
__global__ void __launch_bounds__(256) reduce_kernel(const float* __restrict__ W1){
    int blk = blockIdx.x, tid = threadIdx.x;
    if (blk < 8){
        for (int it = 0; it < 2; it++){
            int e = blk*512 + it*256 + tid;
            float s = 0.0f;
            #pragma unroll 4
            for (int p = 0; p < 128; p++) s += g_Gpart[p*4096 + e];
            g_G[e] = s;
        }
    } else if (blk == 8){
        for (int e = tid; e < NG*COND; e += 256){
            int g = e >> 6, k = e & 63;
            g_s[e] = g_spart[(2*g)*64 + k] + g_spart[(2*g+1)*64 + k];
        }
    } else {
        // blocks 9..16: build g_Bfrag  [nt][ks][lane]{hi,lo}
        int base = (blk - 9)*256 + tid;       // 0..2047
        for (int s = base; s < 4096; s += 2048){
            int lane = s & 31, ks = (s >> 5) & 3, nt = s >> 7;
            int k0 = 16*ks + 2*(lane & 3);
            int n  = nt*8 + (lane >> 2);
            float w0 = W1[(k0    )*D + n];
            float w1 = W1[(k0 + 1)*D + n];
            float w8 = W1[(k0 + 8)*D + n];
            float w9 = W1[(k0 + 9)*D + n];
            u32 h0 = (u32)bf16hi_us(w0) | ((u32)bf16hi_us(w1) << 16);
            u32 h1 = (u32)bf16hi_us(w8) | ((u32)bf16hi_us(w9) << 16);
            u32 l0 = (u32)bf16lo_us(w0) | ((u32)bf16lo_us(w1) << 16);
            u32 l1 = (u32)bf16lo_us(w8) | ((u32)bf16lo_us(w9) << 16);
            g_Bfrag[2*s    ] = (u64)h0 | ((u64)h1 << 32);
            g_Bfrag[2*s + 1] = (u64)l0 | ((u64)l1 << 32);
        }
    }
}

// ================= K2: stats — one column j per block, one graph per thread =================
__global__ void __launch_bounds__(64) stats_kernel(const float* __restrict__ W1,
                                                   const float* __restrict__ b1,
                                                   const float* __restrict__ gamma,
                                                   const float* __restrict__ beta){
    __shared__ float wcol[64];
    __shared__ float wb[128];
    __shared__ float r0s[2], r1s[2], r2s[2];
    int j = blockIdx.x;
    int t = threadIdx.x;        // graph id / k index

    wcol[t]    = W1[t*D + j];
    wb[t]      = W1[(64 + t)*D + j];
    wb[64 + t] = W1[(128 + t)*D + j];
    __syncthreads();

    // wGw partial: colsum_t = sum_s wcol[s] * G[s][t]  (coalesced over t)
    float colsum = 0.0f;
    #pragma unroll 16
    for (int s = 0; s < 64; s++) colsum += wcol[s] * g_G[s*64 + t];
    float wGw_p = colsum * wcol[t];

    // per-graph u and sgw (thread t = graph t)
    float u = b1[j];
    const float4* pp = (const float4*)(g_pooled + t*128);
    #pragma unroll 8
    for (int k4 = 0; k4 < 32; k4++){
        float4 p = pp[k4];
        u += p.x*wb[k4*4] + p.y*wb[k4*4+1] + p.z*wb[k4*4+2] + p.w*wb[k4*4+3];
    }
    g_u[t*D + j] = u;
    float sgw = 0.0f;
    const float4* sp = (const float4*)(g_s + t*64);
    #pragma unroll 4
    for (int k4 = 0; k4 < 16; k4++){
        float4 p = sp[k4];
        sgw += p.x*wcol[k4*4] + p.y*wcol[k4*4+1] + p.z*wcol[k4*4+2] + p.w*wcol[k4*4+3];
    }

    float r0 = sgw + 2048.0f*u;               // -> sum h
    float r1 = 2.0f*u*sgw + 2048.0f*u*u;      // bias part of sum h^2
    float r2 = wGw_p;                          // -> w^T G w
    #pragma unroll
    for (int o = 16; o > 0; o >>= 1){
        r0 += __shfl_down_sync(0xffffffffu, r0, o);
        r1 += __shfl_down_sync(0xffffffffu, r1, o);
        r2 += __shfl_down_sync(0xffffffffu, r2, o);
    }
    if ((t & 31) == 0){
        int w = t >> 5;
        r0s[w] = r0; r1s[w] = r1; r2s[w] = r2;
    }
    __syncthreads();
    if (t == 0){
        const float invN = 1.0f / (float)NTOT;
        float mean  = (r0s[0] + r1s[0]*0.0f + r0s[1]) * invN;
        float sumsq = (r2s[0] + r2s[1]) + (r1s[0] + r1s[1]);
        float var   = sumsq * invN - mean*mean;
        float a = gamma[j] * rsqrtf(var + 1e-5f);
        g_a[j] = a;
        g_c[j] = beta[j] - mean*a;
    }
}

// ================= K3: fused main — mma.sync split-bf16 GEMM + BN + GELU + GEMV =================
// 128 rows per block (2 tiles of 64), B fragments staged once.
__global__ void __launch_bounds__(256) main_kernel(const float* __restrict__ cond,
                                                   const float* __restrict__ W2,
                                                   const float* __restrict__ b2,
                                                   float* __restrict__ out){
    u64*   sB  = (u64*)dsm;                    // 8192 u64 = 64 KB
    float* sA  = dsm + 16384;                  // 64 x MSTRIDE floats
    float* sa  = sA + 64*MSTRIDE;              // 256
    float* sfc = sa + 256;                     // 256
    float* sw2 = sfc + 256;                    // 768
    __shared__ float sred[8][16][3];

    int tid = threadIdx.x, wid = tid >> 5, l = tid & 31;
    int g = blockIdx.x >> 4;                   // 16 blocks per graph (128 rows each)

    // stage B fragments (64 KB) once
    {
        const uint4* src = (const uint4*)g_Bfrag;
        uint4* dst = (uint4*)sB;
        #pragma unroll
        for (int i = tid; i < 4096; i += 256) dst[i] = src[i];
    }
    // coefficients (fold per-graph bias u into the BN offset)
    {
        float a = g_a[tid];
        sa[tid]  = a;
        sfc[tid] = fmaf(g_u[g*D + tid], a, g_c[tid]);
    }
    for (int i = tid; i < 768; i += 256) sw2[i] = W2[i];

    int rbase = (wid >> 1) * 16;               // 4 row groups of 16
    int nth   = (wid & 1);                     // column half (128 cols)
    const uint4* sB4 = (const uint4*)sB;

    #pragma unroll 1
    for (int tile = 0; tile < 2; tile++){
        int row0 = blockIdx.x * 128 + tile * 64;

        // stage A tile (64 rows x 64 f32, padded stride)
        for (int i = tid; i < 1024; i += 256){
            int r = i >> 4, c4 = (i & 15) * 4;
            float4 v = *(const float4*)(cond + (size_t)(row0 + r)*COND + c4);
            float* d = sA + r*MSTRIDE + c4;
            ((float2*)d)[0] = make_float2(v.x, v.y);
            ((float2*)d)[1] = make_float2(v.z, v.w);
        }
        __syncthreads();

        float acc[16][4];
        #pragma unroll
        for (int nt = 0; nt < 16; nt++)
            #pragma unroll
            for (int q = 0; q < 4; q++) acc[nt][q] = 0.0f;

        #pragma unroll
        for (int ks = 0; ks < 4; ks++){
            int c0 = 16*ks + 2*(l & 3);
            int r  = rbase + (l >> 2);
            float2 v00 = *(const float2*)(sA + r*MSTRIDE + c0);
            float2 v10 = *(const float2*)(sA + (r+8)*MSTRIDE + c0);
            float2 v01 = *(const float2*)(sA + r*MSTRIDE + c0 + 8);
            float2 v11 = *(const float2*)(sA + (r+8)*MSTRIDE + c0 + 8);
            u32 ah[4], al[4];
            cvt_hl(v00, ah[0], al[0]);
            cvt_hl(v10, ah[1], al[1]);
            cvt_hl(v01, ah[2], al[2]);
            cvt_hl(v11, ah[3], al[3]);
            const uint4* bp = sB4 + (nth*16*4 + ks)*32 + l;
            #pragma unroll
            for (int nt = 0; nt < 16; nt++){
                uint4 b = bp[nt*128];          // {bh0,bh1,bl0,bl1}
                mma16816(acc[nt], ah, b.x, b.y);
                mma16816(acc[nt], ah, b.z, b.w);
                mma16816(acc[nt], al, b.x, b.y);
            }
        }

        // epilogue: BN + exact GELU + 3-col GEMV partials
        float o0[3] = {0,0,0}, o1[3] = {0,0,0};
        #pragma unroll
        for (int nt = 0; nt < 16; nt++){
            int col = (nth*16 + nt)*8 + 2*(l & 3);
            #pragma unroll
            for (int q = 0; q < 4; q++){
                int c = col + (q & 1);
                float v = acc[nt][q];
                float y = fmaf(v, sa[c], sfc[c]);
                float gl = 0.5f * y * (1.0f + erff(y * 0.70710678118654752f));
                float* o = (q < 2) ? o0 : o1;
                o[0] = fmaf(gl, sw2[c*3 + 0], o[0]);
                o[1] = fmaf(gl, sw2[c*3 + 1], o[1]);
                o[2] = fmaf(gl, sw2[c*3 + 2], o[2]);
            }
        }
        #pragma unroll
        for (int j = 0; j < 3; j++){
            o0[j] += __shfl_xor_sync(0xffffffffu, o0[j], 1);
            o0[j] += __shfl_xor_sync(0xffffffffu, o0[j], 2);
            o1[j] += __shfl_xor_sync(0xffffffffu, o1[j], 1);
            o1[j] += __shfl_xor_sync(0xffffffffu, o1[j], 2);
        }
        if ((l & 3) == 0){
            int rl = l >> 2;
            #pragma unroll
            for (int j = 0; j < 3; j++){
                sred[wid][rl][j]     = o0[j];
                sred[wid][rl + 8][j] = o1[j];
            }
        }
        __syncthreads();
        if (tid < 192){
            int rg = tid / 48, rem = tid % 48, row = rem / 3, j = rem % 3;
            out[((size_t)row0 + rg*16 + row)*3 + j] =
                sred[2*rg][row][j] + sred[2*rg + 1][row][j] + b2[j];
        }
        __syncthreads();
    }
}

// ================= launch =================
extern "C" void kernel_launch(void* const* d_in, const int* in_sizes, int n_in,
                              void* d_out, int out_size){
    const float* x     = (const float*)d_in[0];
    const float* cond  = (const float*)d_in[2];
    const float* W1    = (const float*)d_in[3];
    const float* b1    = (const float*)d_in[4];
    const float* gamma = (const float*)d_in[5];
    const float* beta  = (const float*)d_in[6];
    const float* W2    = (const float*)d_in[7];
    const float* b2    = (const float*)d_in[8];
    float* out = (float*)d_out;

    static int configured = 0;
    if (!configured){
        cudaFuncSetAttribute(gram_kernel, cudaFuncAttributeMaxDynamicSharedMemorySize, 98304);
        cudaFuncSetAttribute(main_kernel, cudaFuncAttributeMaxDynamicSharedMemorySize, 92160);
        configured = 1;
    }

    gram_kernel  <<<128,  256, 98304>>>(cond);
    pool_kernel  <<<1024, 256>>>(x);
    reduce_kernel<<<17,   256>>>(W1);
    stats_kernel <<<256,  64>>>(W1, b1, gamma, beta);
    main_kernel  <<<1024, 256, 87552>>>(cond, W2, b2, out);
}

// round 7
// speedup vs baseline: 1.2615x; 1.0780x over previous
#include <cuda_runtime.h>
#include <cuda_bf16.h>

#define NTOT (64*2048)
#define D    256
#define COND 64
#define NG   64
#define NPG  2048

typedef unsigned long long u64;
typedef unsigned int u32;

// ---------------- device scratch ----------------
__device__ float g_pooled[NG*128];
__device__ float g_u[NG*D];
__device__ float g_Gpart[128*COND*COND];
__device__ float g_spart[128*COND];
__device__ float g_G[COND*COND];
__device__ float g_s[NG*COND];
__device__ float g_a[D];
__device__ float g_c[D];
__device__ uint4 g_WfragH[2048];   // A-operand weight fragments (hi), 32 KB
__device__ uint4 g_WfragL[2048];   // (lo) 32 KB

extern __shared__ float dsm[];

// ---------------- helpers ----------------
__device__ __forceinline__ u64 fma2(u64 a, u64 b, u64 c){
    u64 d; asm("fma.rn.f32x2 %0, %1, %2, %3;" : "=l"(d) : "l"(a), "l"(b), "l"(c)); return d;
}
__device__ __forceinline__ u64 dupf(float v){
    u64 r; asm("mov.b64 %0, {%1, %1};" : "=l"(r) : "f"(v)); return r;
}
__device__ __forceinline__ unsigned short bf16hi_us(float w){
    return __bfloat16_as_ushort(__float2bfloat16(w));
}
__device__ __forceinline__ unsigned short bf16lo_us(float w){
    float r = w - __bfloat162float(__float2bfloat16(w));
    return __bfloat16_as_ushort(__float2bfloat16(r));
}
__device__ __forceinline__ void cvt_hl(float2 v, u32& hi, u32& lo){
    __nv_bfloat162 h = __float22bfloat162_rn(v);
    float2 hf = __bfloat1622float2(h);
    __nv_bfloat162 l2 = __float22bfloat162_rn(make_float2(v.x - hf.x, v.y - hf.y));
    hi = *reinterpret_cast<u32*>(&h);
    lo = *reinterpret_cast<u32*>(&l2);
}
__device__ __forceinline__ void mma16816(float* c, const u32* a, u32 b0, u32 b1){
    asm("mma.sync.aligned.m16n8k16.row.col.f32.bf16.bf16.f32 "
        "{%0,%1,%2,%3}, {%4,%5,%6,%7}, {%8,%9}, {%0,%1,%2,%3};"
        : "+f"(c[0]), "+f"(c[1]), "+f"(c[2]), "+f"(c[3])
        : "r"(a[0]), "r"(a[1]), "r"(a[2]), "r"(a[3]), "r"(b0), "r"(b1));
}

// ================= K0: prep — pool (blocks 0..1023) + Gram (1024..1151), 32KB static smem =================
__global__ void __launch_bounds__(256) prep_kernel(const float* __restrict__ x,
                                                   const float* __restrict__ cond){
    __shared__ float tile[8192];
    int blk = blockIdx.x, tid = threadIdx.x;
    if (blk < 1024){
        int b = blk >> 4, oh = blk & 15;
        const float* p = x + ((size_t)(b*NPG + oh*128))*D + tid;
        float s = 0.0f;
        #pragma unroll 16
        for (int r = 0; r < 128; r++) s += p[(size_t)r*D];
        #pragma unroll
        for (int o = 16; o > 0; o >>= 1) s += __shfl_down_sync(0xffffffffu, s, o);
        if ((tid & 31) == 0) g_pooled[b*128 + oh*8 + (tid >> 5)] = s * (1.0f/4096.0f);
        return;
    }
    int gb = blk - 1024;                      // 0..127 : 1024 rows each
    int ti = tid >> 4, tj = tid & 15;
    int ri = ti*4, cj = tj*4;
    u64 acc[4][2];
    #pragma unroll
    for (int r = 0; r < 4; r++){ acc[r][0] = 0ull; acc[r][1] = 0ull; }
    float ssum = 0.0f;

    for (int sub = 0; sub < 8; sub++){
        size_t base = ((size_t)gb*1024 + sub*128) * COND;
        for (int i = tid; i < 8192; i += 256) tile[i] = cond[base + i];
        __syncthreads();
        #pragma unroll 4
        for (int k = 0; k < 128; k++){
            float4 av = *(const float4*)(tile + k*64 + ri);
            u64 A0 = dupf(av.x), A1 = dupf(av.y), A2 = dupf(av.z), A3 = dupf(av.w);
            ulonglong2 bb = *(const ulonglong2*)(tile + k*64 + cj);
            acc[0][0] = fma2(A0, bb.x, acc[0][0]);
            acc[0][1] = fma2(A0, bb.y, acc[0][1]);
            acc[1][0] = fma2(A1, bb.x, acc[1][0]);
            acc[1][1] = fma2(A1, bb.y, acc[1][1]);
            acc[2][0] = fma2(A2, bb.x, acc[2][0]);
            acc[2][1] = fma2(A2, bb.y, acc[2][1]);
            acc[3][0] = fma2(A3, bb.x, acc[3][0]);
            acc[3][1] = fma2(A3, bb.y, acc[3][1]);
        }
        if (tid < 64){
            #pragma unroll 8
            for (int k = 0; k < 128; k++) ssum += tile[k*64 + tid];
        }
        __syncthreads();
    }
    u64* gp = (u64*)(g_Gpart + (size_t)gb*4096);
    #pragma unroll
    for (int r = 0; r < 4; r++){
        gp[((ri + r)*64 + cj)/2    ] = acc[r][0];
        gp[((ri + r)*64 + cj)/2 + 1] = acc[r][1];
    }
    if (tid < 64) g_spart[gb*64 + tid] = ssum;
}

// ================= K1: reduce Gram/s + build weight A-fragments =================
__global__ void __launch_bounds__(256) reduce_kernel(const float* __restrict__ W1){
    int blk = blockIdx.x, tid = threadIdx.x;
    if (blk < 8){
        for (int it = 0; it < 2; it++){
            int e = blk*512 + it*256 + tid;
            float s = 0.0f;
            #pragma unroll 4
            for (int p = 0; p < 128; p++) s += g_Gpart[p*4096 + e];
            g_G[e] = s;
        }
    } else if (blk == 8){
        for (int e = tid; e < NG*COND; e += 256){
            int g = e >> 6, k = e & 63;
            g_s[e] = g_spart[(2*g)*64 + k] + g_spart[(2*g+1)*64 + k];
        }
    } else {
        // blocks 9..16: A-operand frags of W^T: unit = ((w*2+nt2)*4+ks)*32 + lane
        int unit = (blk - 9)*256 + tid;       // 0..2047
        int lane = unit & 31, ks = (unit >> 5) & 3, ng = unit >> 7;  // ng = w*2+nt2 (0..15)
        int n  = ng*16 + (lane >> 2);
        int k  = ks*16 + 2*(lane & 3);
        float w_k_n   = W1[k*D + n],        w_k1_n  = W1[(k+1)*D + n];
        float w_k_n8  = W1[k*D + n + 8],    w_k1_n8 = W1[(k+1)*D + n + 8];
        float w_k8_n  = W1[(k+8)*D + n],    w_k9_n  = W1[(k+9)*D + n];
        float w_k8_n8 = W1[(k+8)*D + n + 8],w_k9_n8 = W1[(k+9)*D + n + 8];
        uint4 H, L;
        H.x = (u32)bf16hi_us(w_k_n)   | ((u32)bf16hi_us(w_k1_n)  << 16);
        H.y = (u32)bf16hi_us(w_k_n8)  | ((u32)bf16hi_us(w_k1_n8) << 16);
        H.z = (u32)bf16hi_us(w_k8_n)  | ((u32)bf16hi_us(w_k9_n)  << 16);
        H.w = (u32)bf16hi_us(w_k8_n8) | ((u32)bf16hi_us(w_k9_n8) << 16);
        L.x = (u32)bf16lo_us(w_k_n)   | ((u32)bf16lo_us(w_k1_n)  << 16);
        L.y = (u32)bf16lo_us(w_k_n8)  | ((u32)bf16lo_us(w_k1_n8) << 16);
        L.z = (u32)bf16lo_us(w_k8_n)  | ((u32)bf16lo_us(w_k9_n)  << 16);
        L.w = (u32)bf16lo_us(w_k8_n8) | ((u32)bf16lo_us(w_k9_n8) << 16);
        g_WfragH[unit] = H;
        g_WfragL[unit] = L;
    }
}

// ================= K2: stats — block=j, 128 threads (t=graph, h=half) =================
__global__ void __launch_bounds__(128) stats_kernel(const float* __restrict__ W1,
                                                    const float* __restrict__ b1,
                                                    const float* __restrict__ gamma,
                                                    const float* __restrict__ beta){
    __shared__ float wcol[64], wb[128];
    __shared__ float uh[2][64], sgwh[2][64], csh[2][64];
    __shared__ float rs0[4], rs1[4], rs2[4];
    int j = blockIdx.x;
    int tid = threadIdx.x, t = tid & 63, h = tid >> 6;

    if (h == 0) wcol[t] = W1[t*D + j];
    wb[tid] = W1[(64 + tid)*D + j];
    __syncthreads();

    // colsum partial over s-half
    float cs = 0.0f;
    #pragma unroll 8
    for (int s = 0; s < 32; s++) cs += wcol[h*32 + s] * g_G[(h*32 + s)*64 + t];
    csh[h][t] = cs;
    // u partial over k-half (128 -> 64 each)
    float up = (h == 0) ? b1[j] : 0.0f;
    const float4* pp = (const float4*)(g_pooled + t*128 + h*64);
    #pragma unroll 8
    for (int k4 = 0; k4 < 16; k4++){
        float4 p = pp[k4];
        int kb = h*64 + k4*4;
        up += p.x*wb[kb] + p.y*wb[kb+1] + p.z*wb[kb+2] + p.w*wb[kb+3];
    }
    uh[h][t] = up;
    // sgw partial over k-half (64 -> 32 each)
    float sp = 0.0f;
    const float4* spt = (const float4*)(g_s + t*64 + h*32);
    #pragma unroll 4
    for (int k4 = 0; k4 < 8; k4++){
        float4 p = spt[k4];
        int kb = h*32 + k4*4;
        sp += p.x*wcol[kb] + p.y*wcol[kb+1] + p.z*wcol[kb+2] + p.w*wcol[kb+3];
    }
    sgwh[h][t] = sp;
    __syncthreads();

    float r0 = 0.0f, r1 = 0.0f, r2 = 0.0f;
    if (h == 0){
        float u   = uh[0][t] + uh[1][t];
        g_u[t*D + j] = u;
        float sgw = sgwh[0][t] + sgwh[1][t];
        float cst = csh[0][t] + csh[1][t];
        r0 = sgw + 2048.0f*u;
        r1 = 2.0f*u*sgw + 2048.0f*u*u;
        r2 = cst * wcol[t];
    }
    #pragma unroll
    for (int o = 16; o > 0; o >>= 1){
        r0 += __shfl_down_sync(0xffffffffu, r0, o);
        r1 += __shfl_down_sync(0xffffffffu, r1, o);
        r2 += __shfl_down_sync(0xffffffffu, r2, o);
    }
    int wid = tid >> 5, lane = tid & 31;
    if (lane == 0){ rs0[wid] = r0; rs1[wid] = r1; rs2[wid] = r2; }
    __syncthreads();
    if (tid == 0){
        const float invN = 1.0f / (float)NTOT;
        float mean  = (rs0[0] + rs0[1]) * invN;
        float sumsq = (rs2[0] + rs2[1]) + (rs1[0] + rs1[1]);
        float var   = sumsq * invN - mean*mean;
        float a = gamma[j] * rsqrtf(var + 1e-5f);
        g_a[j] = a;
        g_c[j] = beta[j] - mean*a;
    }
}

// ================= K3: fused main — weight-stationary transposed MMA =================
// block: 128 rows. warp w owns n in [w*32, w*32+32). Weights in registers.
__global__ void __launch_bounds__(256) main_kernel(const float* __restrict__ cond,
                                                   const float* __restrict__ W2,
                                                   const float* __restrict__ b2,
                                                   float* __restrict__ out){
    uint4* sF  = (uint4*)dsm;              // [chunk16][ks4][lane32] = 2048 uint4 = 32 KB
    float* sa  = dsm + 8192;               // 256
    float* sfc = sa + 256;                 // 256
    float* sw2 = sfc + 256;                // 768
    float* sprt= sw2 + 768;                // [8][128][3] = 3072 floats

    int tid = threadIdx.x, w = tid >> 5, l = tid & 31;
    int row0 = blockIdx.x * 128;
    int g = blockIdx.x >> 4;

    // coefficients (fold per-graph bias u into BN offset)
    {
        float a = g_a[tid];
        sa[tid]  = a;
        sfc[tid] = fmaf(g_u[g*D + tid], a, g_c[tid]);
    }
    for (int i = tid; i < 768; i += 256) sw2[i] = W2[i];

    // weight fragments -> registers (coalesced LDG.128, once per block)
    uint4 AH[2][4], AL[2][4];
    #pragma unroll
    for (int nt2 = 0; nt2 < 2; nt2++)
        #pragma unroll
        for (int ks = 0; ks < 4; ks++){
            int idx = ((w*2 + nt2)*4 + ks)*32 + l;
            AH[nt2][ks] = g_WfragH[idx];
            AL[nt2][ks] = g_WfragL[idx];
        }

    // build cond B-fragments (bf16 hi/lo) into smem
    #pragma unroll
    for (int i = 0; i < 8; i++){
        int u = tid + i*256;               // 0..2047
        int lane = u & 31, ks = (u >> 5) & 3, chunk = u >> 7;
        int mrow = row0 + chunk*8 + (lane >> 2);
        int k0 = ks*16 + 2*(lane & 3);
        const float* cp = cond + (size_t)mrow*COND + k0;
        float2 v01 = *(const float2*)cp;
        float2 v89 = *(const float2*)(cp + 8);
        u32 bh0, bl0, bh1, bl1;
        cvt_hl(v01, bh0, bl0);
        cvt_hl(v89, bh1, bl1);
        sF[u] = make_uint4(bh0, bh1, bl0, bl1);
    }
    __syncthreads();

    // mainloop: 16 chunks of 8 rows
    #pragma unroll 1
    for (int chunk = 0; chunk < 16; chunk++){
        float acc0[4] = {0,0,0,0}, acc1[4] = {0,0,0,0};
        #pragma unroll
        for (int ks = 0; ks < 4; ks++){
            uint4 f = sF[(chunk*4 + ks)*32 + l];
            mma16816(acc0, (const u32*)&AH[0][ks], f.x, f.y);
            mma16816(acc0, (const u32*)&AH[0][ks], f.z, f.w);
            mma16816(acc0, (const u32*)&AL[0][ks], f.x, f.y);
            mma16816(acc1, (const u32*)&AH[1][ks], f.x, f.y);
            mma16816(acc1, (const u32*)&AH[1][ks], f.z, f.w);
            mma16816(acc1, (const u32*)&AL[1][ks], f.x, f.y);
        }
        // epilogue: BN + exact GELU + GEMV partials (n resides in this warp)
        float po0[3] = {0,0,0}, po1[3] = {0,0,0};
        #pragma unroll
        for (int nt2 = 0; nt2 < 2; nt2++){
            const float* ac = nt2 ? acc1 : acc0;
            int nb = w*32 + nt2*16 + (l >> 2);
            #pragma unroll
            for (int q = 0; q < 4; q++){
                int n = nb + ((q >= 2) ? 8 : 0);
                float v = ac[q];
                float y = fmaf(v, sa[n], sfc[n]);
                float gl = 0.5f * y * (1.0f + erff(y * 0.70710678118654752f));
                float* po = (q & 1) ? po1 : po0;
                po[0] = fmaf(gl, sw2[n*3 + 0], po[0]);
                po[1] = fmaf(gl, sw2[n*3 + 1], po[1]);
                po[2] = fmaf(gl, sw2[n*3 + 2], po[2]);
            }
        }
        #pragma unroll
        for (int j = 0; j < 3; j++){
            #pragma unroll
            for (int o = 4; o < 32; o <<= 1){
                po0[j] += __shfl_xor_sync(0xffffffffu, po0[j], o);
                po1[j] += __shfl_xor_sync(0xffffffffu, po1[j], o);
            }
        }
        if (l < 4){
            int r0 = chunk*8 + 2*l;
            #pragma unroll
            for (int j = 0; j < 3; j++){
                sprt[(w*128 + r0    )*3 + j] = po0[j];
                sprt[(w*128 + r0 + 1)*3 + j] = po1[j];
            }
        }
    }
    __syncthreads();

    // final: sum 8 warp partials per (row, j)
    for (int o = tid; o < 384; o += 256){
        float s = b2[o % 3];
        #pragma unroll
        for (int wi = 0; wi < 8; wi++) s += sprt[wi*384 + o];
        out[(size_t)row0*3 + o] = s;
    }
}

// ================= launch =================
extern "C" void kernel_launch(void* const* d_in, const int* in_sizes, int n_in,
                              void* d_out, int out_size){
    const float* x     = (const float*)d_in[0];
    const float* cond  = (const float*)d_in[2];
    const float* W1    = (const float*)d_in[3];
    const float* b1    = (const float*)d_in[4];
    const float* gamma = (const float*)d_in[5];
    const float* beta  = (const float*)d_in[6];
    const float* W2    = (const float*)d_in[7];
    const float* b2    = (const float*)d_in[8];
    float* out = (float*)d_out;

    static int configured = 0;
    if (!configured){
        cudaFuncSetAttribute(main_kernel, cudaFuncAttributeMaxDynamicSharedMemorySize, 50176);
        configured = 1;
    }

    prep_kernel  <<<1152, 256>>>(x, cond);
    reduce_kernel<<<17,   256>>>(W1);
    stats_kernel <<<256,  128>>>(W1, b1, gamma, beta);
    main_kernel  <<<1024, 256, 50176>>>(cond, W2, b2, out);
}

// round 8
// speedup vs baseline: 1.3082x; 1.0370x over previous
#include <cuda_runtime.h>
#include <cuda_bf16.h>

#define NTOT (64*2048)
#define D    256
#define COND 64
#define NG   64
#define NPG  2048

typedef unsigned long long u64;
typedef unsigned int u32;

// ---------------- device scratch ----------------
__device__ float g_pooled[NG*128];
__device__ float g_u[NG*D];
__device__ float g_Gpart[128*COND*COND];
__device__ float g_spart[128*COND];
__device__ float g_G[COND*COND];
__device__ float g_s[NG*COND];
__device__ float g_a[D];
__device__ float g_c[D];
__device__ uint4 g_WfragH[2048];   // A-operand weight fragments (hi), 32 KB
__device__ uint4 g_WfragL[2048];   // (lo) 32 KB

extern __shared__ float dsm[];

// ---------------- f32x2 + misc helpers ----------------
__device__ __forceinline__ u64 fma2(u64 a, u64 b, u64 c){
    u64 d; asm("fma.rn.f32x2 %0, %1, %2, %3;" : "=l"(d) : "l"(a), "l"(b), "l"(c)); return d;
}
__device__ __forceinline__ u64 mul2(u64 a, u64 b){
    u64 d; asm("mul.rn.f32x2 %0, %1, %2;" : "=l"(d) : "l"(a), "l"(b)); return d;
}
__device__ __forceinline__ u64 add2(u64 a, u64 b){
    u64 d; asm("add.rn.f32x2 %0, %1, %2;" : "=l"(d) : "l"(a), "l"(b)); return d;
}
__device__ __forceinline__ u64 dup2(float v){
    u64 r; asm("mov.b64 %0, {%1, %1};" : "=l"(r) : "f"(v)); return r;
}
__device__ __forceinline__ u64 pk2(float x, float y){
    u64 r; asm("mov.b64 %0, {%1, %2};" : "=l"(r) : "f"(x), "f"(y)); return r;
}
__device__ __forceinline__ float2 upk2(u64 v){
    float2 f; asm("mov.b64 {%0, %1}, %2;" : "=f"(f.x), "=f"(f.y) : "l"(v)); return f;
}
__device__ __forceinline__ float rcp_f(float x){
    float r; asm("rcp.approx.f32 %0, %1;" : "=f"(r) : "f"(x)); return r;
}
__device__ __forceinline__ float ex2_f(float x){
    float r; asm("ex2.approx.f32 %0, %1;" : "=f"(r) : "f"(x)); return r;
}
__device__ __forceinline__ unsigned short bf16hi_us(float w){
    return __bfloat16_as_ushort(__float2bfloat16(w));
}
__device__ __forceinline__ unsigned short bf16lo_us(float w){
    float r = w - __bfloat162float(__float2bfloat16(w));
    return __bfloat16_as_ushort(__float2bfloat16(r));
}
__device__ __forceinline__ void cvt_hl(float2 v, u32& hi, u32& lo){
    __nv_bfloat162 h = __float22bfloat162_rn(v);
    float2 hf = __bfloat1622float2(h);
    __nv_bfloat162 l2 = __float22bfloat162_rn(make_float2(v.x - hf.x, v.y - hf.y));
    hi = *reinterpret_cast<u32*>(&h);
    lo = *reinterpret_cast<u32*>(&l2);
}
__device__ __forceinline__ void mma16816(float* c, const u32* a, u32 b0, u32 b1){
    asm("mma.sync.aligned.m16n8k16.row.col.f32.bf16.bf16.f32 "
        "{%0,%1,%2,%3}, {%4,%5,%6,%7}, {%8,%9}, {%0,%1,%2,%3};"
        : "+f"(c[0]), "+f"(c[1]), "+f"(c[2]), "+f"(c[3])
        : "r"(a[0]), "r"(a[1]), "r"(a[2]), "r"(a[3]), "r"(b0), "r"(b1));
}

// Packed exact-GELU via A&S 7.1.26 erf (abs err ~1.5e-7):
// gelu(y) = 0.5*(y + |y|) - 0.5*|y|*P(t)*exp(-y^2/2),  t = 1/(1+p*|y|/sqrt2)
__device__ __forceinline__ u64 gelu2(u64 y2){
    u64 ay2 = y2 & 0x7FFFFFFF7FFFFFFFull;
    u64 xx2 = mul2(y2, y2);
    u64 earg= mul2(xx2, dup2(-0.72134752044448170f));   // -y^2 * log2(e)/2
    u64 ax2 = mul2(ay2, dup2(0.70710678118654752f));
    u64 den = fma2(ax2, dup2(0.3275911f), dup2(1.0f));
    float2 dv = upk2(den);
    u64 t2 = pk2(rcp_f(dv.x), rcp_f(dv.y));
    u64 P  = fma2(t2, dup2(1.061405429f), dup2(-1.453152027f));
    P = fma2(P, t2, dup2( 1.421413741f));
    P = fma2(P, t2, dup2(-0.284496736f));
    P = fma2(P, t2, dup2( 0.254829592f));
    P = mul2(P, t2);
    float2 ev = upk2(earg);
    u64 e2 = pk2(ex2_f(ev.x), ex2_f(ev.y));
    u64 s2 = mul2(mul2(ay2, P), e2);
    u64 r2 = add2(y2, ay2);
    u64 d2 = add2(r2, s2 ^ 0x8000000080000000ull);
    return mul2(d2, dup2(0.5f));
}

// ================= K0: prep — pool (blocks 0..1023) + Gram (1024..1151) =================
__global__ void __launch_bounds__(256) prep_kernel(const float* __restrict__ x,
                                                   const float* __restrict__ cond){
    __shared__ float tile[8192];
    int blk = blockIdx.x, tid = threadIdx.x;
    if (blk < 1024){
        int b = blk >> 4, oh = blk & 15;
        const float* p = x + ((size_t)(b*NPG + oh*128))*D + tid;
        float s = 0.0f;
        #pragma unroll 16
        for (int r = 0; r < 128; r++) s += p[(size_t)r*D];
        #pragma unroll
        for (int o = 16; o > 0; o >>= 1) s += __shfl_down_sync(0xffffffffu, s, o);
        if ((tid & 31) == 0) g_pooled[b*128 + oh*8 + (tid >> 5)] = s * (1.0f/4096.0f);
        return;
    }
    int gb = blk - 1024;
    int ti = tid >> 4, tj = tid & 15;
    int ri = ti*4, cj = tj*4;
    u64 acc[4][2];
    #pragma unroll
    for (int r = 0; r < 4; r++){ acc[r][0] = 0ull; acc[r][1] = 0ull; }
    float ssum = 0.0f;

    for (int sub = 0; sub < 8; sub++){
        size_t base = ((size_t)gb*1024 + sub*128) * COND;
        for (int i = tid; i < 8192; i += 256) tile[i] = cond[base + i];
        __syncthreads();
        #pragma unroll 4
        for (int k = 0; k < 128; k++){
            float4 av = *(const float4*)(tile + k*64 + ri);
            u64 A0 = dup2(av.x), A1 = dup2(av.y), A2 = dup2(av.z), A3 = dup2(av.w);
            ulonglong2 bb = *(const ulonglong2*)(tile + k*64 + cj);
            acc[0][0] = fma2(A0, bb.x, acc[0][0]);
            acc[0][1] = fma2(A0, bb.y, acc[0][1]);
            acc[1][0] = fma2(A1, bb.x, acc[1][0]);
            acc[1][1] = fma2(A1, bb.y, acc[1][1]);
            acc[2][0] = fma2(A2, bb.x, acc[2][0]);
            acc[2][1] = fma2(A2, bb.y, acc[2][1]);
            acc[3][0] = fma2(A3, bb.x, acc[3][0]);
            acc[3][1] = fma2(A3, bb.y, acc[3][1]);
        }
        if (tid < 64){
            #pragma unroll 8
            for (int k = 0; k < 128; k++) ssum += tile[k*64 + tid];
        }
        __syncthreads();
    }
    u64* gp = (u64*)(g_Gpart + (size_t)gb*4096);
    #pragma unroll
    for (int r = 0; r < 4; r++){
        gp[((ri + r)*64 + cj)/2    ] = acc[r][0];
        gp[((ri + r)*64 + cj)/2 + 1] = acc[r][1];
    }
    if (tid < 64) g_spart[gb*64 + tid] = ssum;
}

// ================= K1: reduce Gram/s + build weight A-fragments =================
__global__ void __launch_bounds__(256) reduce_kernel(const float* __restrict__ W1){
    int blk = blockIdx.x, tid = threadIdx.x;
    if (blk < 8){
        for (int it = 0; it < 2; it++){
            int e = blk*512 + it*256 + tid;
            float s = 0.0f;
            #pragma unroll 4
            for (int p = 0; p < 128; p++) s += g_Gpart[p*4096 + e];
            g_G[e] = s;
        }
    } else if (blk == 8){
        for (int e = tid; e < NG*COND; e += 256){
            int g = e >> 6, k = e & 63;
            g_s[e] = g_spart[(2*g)*64 + k] + g_spart[(2*g+1)*64 + k];
        }
    } else {
        int unit = (blk - 9)*256 + tid;       // 0..2047
        int lane = unit & 31, ks = (unit >> 5) & 3, ng = unit >> 7;
        int n  = ng*16 + (lane >> 2);
        int k  = ks*16 + 2*(lane & 3);
        float w_k_n   = W1[k*D + n],        w_k1_n  = W1[(k+1)*D + n];
        float w_k_n8  = W1[k*D + n + 8],    w_k1_n8 = W1[(k+1)*D + n + 8];
        float w_k8_n  = W1[(k+8)*D + n],    w_k9_n  = W1[(k+9)*D + n];
        float w_k8_n8 = W1[(k+8)*D + n + 8],w_k9_n8 = W1[(k+9)*D + n + 8];
        uint4 H, L;
        H.x = (u32)bf16hi_us(w_k_n)   | ((u32)bf16hi_us(w_k1_n)  << 16);
        H.y = (u32)bf16hi_us(w_k_n8)  | ((u32)bf16hi_us(w_k1_n8) << 16);
        H.z = (u32)bf16hi_us(w_k8_n)  | ((u32)bf16hi_us(w_k9_n)  << 16);
        H.w = (u32)bf16hi_us(w_k8_n8) | ((u32)bf16hi_us(w_k9_n8) << 16);
        L.x = (u32)bf16lo_us(w_k_n)   | ((u32)bf16lo_us(w_k1_n)  << 16);
        L.y = (u32)bf16lo_us(w_k_n8)  | ((u32)bf16lo_us(w_k1_n8) << 16);
        L.z = (u32)bf16lo_us(w_k8_n)  | ((u32)bf16lo_us(w_k9_n)  << 16);
        L.w = (u32)bf16lo_us(w_k8_n8) | ((u32)bf16lo_us(w_k9_n8) << 16);
        g_WfragH[unit] = H;
        g_WfragL[unit] = L;
    }
}

// ================= K2: stats — block=j, 128 threads (t=graph, h=half) =================
__global__ void __launch_bounds__(128) stats_kernel(const float* __restrict__ W1,
                                                    const float* __restrict__ b1,
                                                    const float* __restrict__ gamma,
                                                    const float* __restrict__ beta){
    __shared__ float wcol[64], wb[128];
    __shared__ float uh[2][64], sgwh[2][64], csh[2][64];
    __shared__ float rs0[4], rs1[4], rs2[4];
    int j = blockIdx.x;
    int tid = threadIdx.x, t = tid & 63, h = tid >> 6;

    if (h == 0) wcol[t] = W1[t*D + j];
    wb[tid] = W1[(64 + tid)*D + j];
    __syncthreads();

    float cs = 0.0f;
    #pragma unroll 8
    for (int s = 0; s < 32; s++) cs += wcol[h*32 + s] * g_G[(h*32 + s)*64 + t];
    csh[h][t] = cs;
    float up = (h == 0) ? b1[j] : 0.0f;
    const float4* pp = (const float4*)(g_pooled + t*128 + h*64);
    #pragma unroll 8
    for (int k4 = 0; k4 < 16; k4++){
        float4 p = pp[k4];
        int kb = h*64 + k4*4;
        up += p.x*wb[kb] + p.y*wb[kb+1] + p.z*wb[kb+2] + p.w*wb[kb+3];
    }
    uh[h][t] = up;
    float sp = 0.0f;
    const float4* spt = (const float4*)(g_s + t*64 + h*32);
    #pragma unroll 4
    for (int k4 = 0; k4 < 8; k4++){
        float4 p = spt[k4];
        int kb = h*32 + k4*4;
        sp += p.x*wcol[kb] + p.y*wcol[kb+1] + p.z*wcol[kb+2] + p.w*wcol[kb+3];
    }
    sgwh[h][t] = sp;
    __syncthreads();

    float r0 = 0.0f, r1 = 0.0f, r2 = 0.0f;
    if (h == 0){
        float u   = uh[0][t] + uh[1][t];
        g_u[t*D + j] = u;
        float sgw = sgwh[0][t] + sgwh[1][t];
        float cst = csh[0][t] + csh[1][t];
        r0 = sgw + 2048.0f*u;
        r1 = 2.0f*u*sgw + 2048.0f*u*u;
        r2 = cst * wcol[t];
    }
    #pragma unroll
    for (int o = 16; o > 0; o >>= 1){
        r0 += __shfl_down_sync(0xffffffffu, r0, o);
        r1 += __shfl_down_sync(0xffffffffu, r1, o);
        r2 += __shfl_down_sync(0xffffffffu, r2, o);
    }
    int wid = tid >> 5, lane = tid & 31;
    if (lane == 0){ rs0[wid] = r0; rs1[wid] = r1; rs2[wid] = r2; }
    __syncthreads();
    if (tid == 0){
        const float invN = 1.0f / (float)NTOT;
        float mean  = (rs0[0] + rs0[1]) * invN;
        float sumsq = (rs2[0] + rs2[1]) + (rs1[0] + rs1[1]);
        float var   = sumsq * invN - mean*mean;
        float a = gamma[j] * rsqrtf(var + 1e-5f);
        g_a[j] = a;
        g_c[j] = beta[j] - mean*a;
    }
}

// ================= K3: fused main — weight-stationary MMA, packed f32x2 epilogue =================
// block: 64 rows, 8 warps; warp w owns n in [w*32, w*32+32).
// ks 0,1 weight frags in registers; ks 2,3 streamed from smem. 3 blocks/SM.
__global__ void __launch_bounds__(256, 3) main_kernel(const float* __restrict__ cond,
                                                      const float* __restrict__ W2,
                                                      const float* __restrict__ b2,
                                                      float* __restrict__ out){
    uint4* sF  = (uint4*)dsm;              // [chunk8][ks4][lane32] = 1024 uint4 = 16 KB
    uint4* sWH = (uint4*)(dsm + 4096);     // [ng16][ks2(2,3)][lane32] = 1024 uint4 = 16 KB
    uint4* sWL = (uint4*)(dsm + 8192);     // 16 KB
    float* sa  = dsm + 12288;              // 256
    float* sfc = sa + 256;                 // 256
    float* sw2 = sfc + 256;                // 768
    float* sprt= sw2 + 768;                // [8][64][3] = 1536 floats

    int tid = threadIdx.x, w = tid >> 5, l = tid & 31;
    int row0 = blockIdx.x * 64;
    int g = blockIdx.x >> 5;               // 32 blocks per graph

    // coefficients (fold per-graph bias u into BN offset)
    {
        float a = g_a[tid];
        sa[tid]  = a;
        sfc[tid] = fmaf(g_u[g*D + tid], a, g_c[tid]);
    }
    for (int i = tid; i < 768; i += 256) sw2[i] = W2[i];

    // ks 0,1 weight fragments -> registers
    uint4 AH[2][2], AL[2][2];
    #pragma unroll
    for (int nt2 = 0; nt2 < 2; nt2++)
        #pragma unroll
        for (int ks = 0; ks < 2; ks++){
            int idx = ((w*2 + nt2)*4 + ks)*32 + l;
            AH[nt2][ks] = g_WfragH[idx];
            AL[nt2][ks] = g_WfragL[idx];
        }
    // ks 2,3 weight fragments -> smem
    #pragma unroll
    for (int i = 0; i < 4; i++){
        int u = tid + i*256;               // 0..1023
        int lane = u & 31, ks2 = (u >> 5) & 1, ng = u >> 6;
        int src = (ng*4 + 2 + ks2)*32 + lane;
        sWH[u] = g_WfragH[src];
        sWL[u] = g_WfragL[src];
    }

    // build cond B-fragments (bf16 hi/lo) into smem: 64 rows
    #pragma unroll
    for (int i = 0; i < 4; i++){
        int u = tid + i*256;               // 0..1023
        int lane = u & 31, ks = (u >> 5) & 3, chunk = u >> 7;
        int mrow = row0 + chunk*8 + (lane >> 2);
        int k0 = ks*16 + 2*(lane & 3);
        const float* cp = cond + (size_t)mrow*COND + k0;
        float2 v01 = *(const float2*)cp;
        float2 v89 = *(const float2*)(cp + 8);
        u32 bh0, bl0, bh1, bl1;
        cvt_hl(v01, bh0, bl0);
        cvt_hl(v89, bh1, bl1);
        sF[u] = make_uint4(bh0, bh1, bl0, bl1);
    }
    __syncthreads();

    // per-thread packed BN/GEMV coefficients (n fixed per thread)
    u64 ca2[2], cc2[2], cw2[2][3];
    #pragma unroll
    for (int nt2 = 0; nt2 < 2; nt2++){
        int n0 = w*32 + nt2*16 + (l >> 2);
        ca2[nt2] = pk2(sa[n0], sa[n0 + 8]);
        cc2[nt2] = pk2(sfc[n0], sfc[n0 + 8]);
        #pragma unroll
        for (int j = 0; j < 3; j++)
            cw2[nt2][j] = pk2(sw2[n0*3 + j], sw2[(n0+8)*3 + j]);
    }

    // mainloop: 8 chunks of 8 rows
    #pragma unroll 1
    for (int chunk = 0; chunk < 8; chunk++){
        float acc[2][4] = {{0,0,0,0},{0,0,0,0}};
        #pragma unroll
        for (int ks = 0; ks < 4; ks++){
            uint4 f = sF[(chunk*4 + ks)*32 + l];
            #pragma unroll
            for (int nt2 = 0; nt2 < 2; nt2++){
                uint4 wh, wl;
                if (ks < 2){ wh = AH[nt2][ks]; wl = AL[nt2][ks]; }
                else {
                    int idx = ((w*2 + nt2)*2 + (ks - 2))*32 + l;
                    wh = sWH[idx]; wl = sWL[idx];
                }
                mma16816(acc[nt2], (const u32*)&wh, f.x, f.y);
                mma16816(acc[nt2], (const u32*)&wh, f.z, f.w);
                mma16816(acc[nt2], (const u32*)&wl, f.x, f.y);
            }
        }
        // packed epilogue: BN + GELU + GEMV, pairs (n, n+8)
        u64 poc[3] = {0,0,0}, pod[3] = {0,0,0};
        #pragma unroll
        for (int nt2 = 0; nt2 < 2; nt2++){
            #pragma unroll
            for (int q = 0; q < 2; q++){
                u64 v2 = pk2(acc[nt2][q], acc[nt2][q + 2]);
                u64 y2 = fma2(v2, ca2[nt2], cc2[nt2]);
                u64 g2 = gelu2(y2);
                u64* po = q ? pod : poc;
                po[0] = fma2(g2, cw2[nt2][0], po[0]);
                po[1] = fma2(g2, cw2[nt2][1], po[1]);
                po[2] = fma2(g2, cw2[nt2][2], po[2]);
            }
        }
        // unpack + sum halves, then reduce over n-groups (l>>2)
        float oc[3], od[3];
        #pragma unroll
        for (int j = 0; j < 3; j++){
            float2 a = upk2(poc[j]); oc[j] = a.x + a.y;
            float2 b = upk2(pod[j]); od[j] = b.x + b.y;
        }
        #pragma unroll
        for (int j = 0; j < 3; j++){
            #pragma unroll
            for (int o = 4; o < 32; o <<= 1){
                oc[j] += __shfl_xor_sync(0xffffffffu, oc[j], o);
                od[j] += __shfl_xor_sync(0xffffffffu, od[j], o);
            }
        }
        if (l < 4){
            int r0 = chunk*8 + 2*l;
            #pragma unroll
            for (int j = 0; j < 3; j++){
                sprt[(w*64 + r0    )*3 + j] = oc[j];
                sprt[(w*64 + r0 + 1)*3 + j] = od[j];
            }
        }
    }
    __syncthreads();

    // final: sum 8 warp partials per (row, j); 64 rows x 3 = 192 outputs
    if (tid < 192){
        float s = b2[tid % 3];
        #pragma unroll
        for (int wi = 0; wi < 8; wi++) s += sprt[wi*192 + tid];
        out[(size_t)row0*3 + tid] = s;
    }
}

// ================= launch =================
extern "C" void kernel_launch(void* const* d_in, const int* in_sizes, int n_in,
                              void* d_out, int out_size){
    const float* x     = (const float*)d_in[0];
    const float* cond  = (const float*)d_in[2];
    const float* W1    = (const float*)d_in[3];
    const float* b1    = (const float*)d_in[4];
    const float* gamma = (const float*)d_in[5];
    const float* beta  = (const float*)d_in[6];
    const float* W2    = (const float*)d_in[7];
    const float* b2    = (const float*)d_in[8];
    float* out = (float*)d_out;

    static int configured = 0;
    if (!configured){
        cudaFuncSetAttribute(main_kernel, cudaFuncAttributeMaxDynamicSharedMemorySize, 60416);
        configured = 1;
    }

    prep_kernel  <<<1152, 256>>>(x, cond);
    reduce_kernel<<<17,   256>>>(W1);
    stats_kernel <<<256,  128>>>(W1, b1, gamma, beta);
    main_kernel  <<<2048, 256, 60416>>>(cond, W2, b2, out);
}

// round 9
// speedup vs baseline: 1.9145x; 1.4635x over previous
#include <cuda_runtime.h>
#include <cuda_bf16.h>

#define NTOT (64*2048)
#define D    256
#define COND 64
#define NG   64
#define NPG  2048

typedef unsigned long long u64;
typedef unsigned int u32;

// ---------------- device scratch ----------------
__device__ float g_pooled[NG*128];
__device__ float g_u[NG*D];
__device__ float g_G[COND*COND];      // atomic-accumulated Gram (zeroed by main each run)
__device__ float g_s[NG*COND];        // atomic-accumulated per-graph col sums
__device__ float g_a[D];
__device__ float g_c[D];
__device__ uint4 g_WfragH[2048];
__device__ uint4 g_WfragL[2048];

extern __shared__ float dsm[];

// ---------------- f32x2 + misc helpers ----------------
__device__ __forceinline__ u64 fma2(u64 a, u64 b, u64 c){
    u64 d; asm("fma.rn.f32x2 %0, %1, %2, %3;" : "=l"(d) : "l"(a), "l"(b), "l"(c)); return d;
}
__device__ __forceinline__ u64 mul2(u64 a, u64 b){
    u64 d; asm("mul.rn.f32x2 %0, %1, %2;" : "=l"(d) : "l"(a), "l"(b)); return d;
}
__device__ __forceinline__ u64 add2(u64 a, u64 b){
    u64 d; asm("add.rn.f32x2 %0, %1, %2;" : "=l"(d) : "l"(a), "l"(b)); return d;
}
__device__ __forceinline__ u64 dup2(float v){
    u64 r; asm("mov.b64 %0, {%1, %1};" : "=l"(r) : "f"(v)); return r;
}
__device__ __forceinline__ u64 pk2(float x, float y){
    u64 r; asm("mov.b64 %0, {%1, %2};" : "=l"(r) : "f"(x), "f"(y)); return r;
}
__device__ __forceinline__ float2 upk2(u64 v){
    float2 f; asm("mov.b64 {%0, %1}, %2;" : "=f"(f.x), "=f"(f.y) : "l"(v)); return f;
}
__device__ __forceinline__ unsigned short bf16hi_us(float w){
    return __bfloat16_as_ushort(__float2bfloat16(w));
}
__device__ __forceinline__ unsigned short bf16lo_us(float w){
    float r = w - __bfloat162float(__float2bfloat16(w));
    return __bfloat16_as_ushort(__float2bfloat16(r));
}
__device__ __forceinline__ void cvt_hl(float2 v, u32& hi, u32& lo){
    __nv_bfloat162 h = __float22bfloat162_rn(v);
    float2 hf = __bfloat1622float2(h);
    __nv_bfloat162 l2 = __float22bfloat162_rn(make_float2(v.x - hf.x, v.y - hf.y));
    hi = *reinterpret_cast<u32*>(&h);
    lo = *reinterpret_cast<u32*>(&l2);
}
__device__ __forceinline__ void mma16816(float* c, const u32* a, u32 b0, u32 b1){
    asm("mma.sync.aligned.m16n8k16.row.col.f32.bf16.bf16.f32 "
        "{%0,%1,%2,%3}, {%4,%5,%6,%7}, {%8,%9}, {%0,%1,%2,%3};"
        : "+f"(c[0]), "+f"(c[1]), "+f"(c[2]), "+f"(c[3])
        : "r"(a[0]), "r"(a[1]), "r"(a[2]), "r"(a[3]), "r"(b0), "r"(b1));
}

// Packed tanh-form GELU using MUFU.TANH (7 instr + 2 MUFU per pair)
__device__ __forceinline__ u64 gelu2t(u64 y2){
    u64 xx    = mul2(y2, y2);
    u64 inner = fma2(xx, dup2(0.044715f), dup2(1.0f));
    u64 arg   = mul2(mul2(y2, inner), dup2(0.79788456080286536f));
    float2 av = upk2(arg);
    float t0, t1;
    asm("tanh.approx.f32 %0, %1;" : "=f"(t0) : "f"(av.x));
    asm("tanh.approx.f32 %0, %1;" : "=f"(t1) : "f"(av.y));
    u64 half = fma2(pk2(t0, t1), dup2(0.5f), dup2(0.5f));
    return mul2(y2, half);
}

// ================= K0: prep — pool(0..1023) + gram(1024..1279) + wfrag(1280..1287) =================
__global__ void __launch_bounds__(256) prep_kernel(const float* __restrict__ x,
                                                   const float* __restrict__ cond,
                                                   const float* __restrict__ W1){
    __shared__ float tile[8192];
    int blk = blockIdx.x, tid = threadIdx.x;

    if (blk < 1024){
        // ---- pool: block = (graph b, oh); thread = (col4 c4, row-group rg) ----
        int b = blk >> 4, oh = blk & 15;
        int c4 = tid & 63, rg = tid >> 6;
        const ulonglong2* p = (const ulonglong2*)(x + ((size_t)(b*NPG + oh*128 + rg))*D) + c4;
        u64 s01 = 0ull, s23 = 0ull;
        #pragma unroll 8
        for (int k = 0; k < 32; k++){
            ulonglong2 v = p[(size_t)k*256];   // 4 rows * 256 floats = 256 ulonglong2
            s01 = add2(s01, v.x);
            s23 = add2(s23, v.y);
        }
        ulonglong2* sp = (ulonglong2*)tile;
        sp[tid] = make_ulonglong2(s01, s23);
        __syncthreads();
        if (tid < 64){
            ulonglong2 a = sp[tid], b2v = sp[tid+64], c = sp[tid+128], d = sp[tid+192];
            u64 t01 = add2(add2(a.x, b2v.x), add2(c.x, d.x));
            u64 t23 = add2(add2(a.y, b2v.y), add2(c.y, d.y));
            float2 f01 = upk2(t01), f23 = upk2(t23);
            float t = (f01.x + f01.y) + (f23.x + f23.y);
            t += __shfl_down_sync(0xffffffffu, t, 4, 8);
            t += __shfl_down_sync(0xffffffffu, t, 2, 8);
            t += __shfl_down_sync(0xffffffffu, t, 1, 8);
            if ((tid & 7) == 0) g_pooled[b*128 + oh*8 + (tid >> 3)] = t * (1.0f/4096.0f);
        }
        return;
    }
    if (blk < 1280){
        // ---- gram: 256 blocks x 512 rows, atomic accumulate into g_G / g_s ----
        int gb = blk - 1024;
        int ti = tid >> 4, tj = tid & 15;
        int ri = ti*4, cj = tj*4;
        u64 acc[4][2];
        #pragma unroll
        for (int r = 0; r < 4; r++){ acc[r][0] = 0ull; acc[r][1] = 0ull; }
        float ssum = 0.0f;

        for (int sub = 0; sub < 4; sub++){
            size_t base = ((size_t)gb*512 + sub*128) * COND;
            for (int i = tid; i < 8192; i += 256) tile[i] = cond[base + i];
            __syncthreads();
            #pragma unroll 4
            for (int k = 0; k < 128; k++){
                float4 av = *(const float4*)(tile + k*64 + ri);
                u64 A0 = dup2(av.x), A1 = dup2(av.y), A2 = dup2(av.z), A3 = dup2(av.w);
                ulonglong2 bb = *(const ulonglong2*)(tile + k*64 + cj);
                acc[0][0] = fma2(A0, bb.x, acc[0][0]);
                acc[0][1] = fma2(A0, bb.y, acc[0][1]);
                acc[1][0] = fma2(A1, bb.x, acc[1][0]);
                acc[1][1] = fma2(A1, bb.y, acc[1][1]);
                acc[2][0] = fma2(A2, bb.x, acc[2][0]);
                acc[2][1] = fma2(A2, bb.y, acc[2][1]);
                acc[3][0] = fma2(A3, bb.x, acc[3][0]);
                acc[3][1] = fma2(A3, bb.y, acc[3][1]);
            }
            if (tid < 64){
                #pragma unroll 8
                for (int k = 0; k < 128; k++) ssum += tile[k*64 + tid];
            }
            __syncthreads();
        }
        #pragma unroll
        for (int r = 0; r < 4; r++){
            float2 v0 = upk2(acc[r][0]);
            float2 v1 = upk2(acc[r][1]);
            atomicAdd(&g_G[(ri + r)*64 + cj + 0], v0.x);
            atomicAdd(&g_G[(ri + r)*64 + cj + 1], v0.y);
            atomicAdd(&g_G[(ri + r)*64 + cj + 2], v1.x);
            atomicAdd(&g_G[(ri + r)*64 + cj + 3], v1.y);
        }
        if (tid < 64) atomicAdd(&g_s[(gb >> 2)*64 + tid], ssum);
        return;
    }
    // ---- wfrag: blocks 1280..1287 build weight A-fragments ----
    {
        int unit = (blk - 1280)*256 + tid;    // 0..2047
        int lane = unit & 31, ks = (unit >> 5) & 3, ng = unit >> 7;
        int n  = ng*16 + (lane >> 2);
        int k  = ks*16 + 2*(lane & 3);
        float w_k_n   = W1[k*D + n],        w_k1_n  = W1[(k+1)*D + n];
        float w_k_n8  = W1[k*D + n + 8],    w_k1_n8 = W1[(k+1)*D + n + 8];
        float w_k8_n  = W1[(k+8)*D + n],    w_k9_n  = W1[(k+9)*D + n];
        float w_k8_n8 = W1[(k+8)*D + n + 8],w_k9_n8 = W1[(k+9)*D + n + 8];
        uint4 H, L;
        H.x = (u32)bf16hi_us(w_k_n)   | ((u32)bf16hi_us(w_k1_n)  << 16);
        H.y = (u32)bf16hi_us(w_k_n8)  | ((u32)bf16hi_us(w_k1_n8) << 16);
        H.z = (u32)bf16hi_us(w_k8_n)  | ((u32)bf16hi_us(w_k9_n)  << 16);
        H.w = (u32)bf16hi_us(w_k8_n8) | ((u32)bf16hi_us(w_k9_n8) << 16);
        L.x = (u32)bf16lo_us(w_k_n)   | ((u32)bf16lo_us(w_k1_n)  << 16);
        L.y = (u32)bf16lo_us(w_k_n8)  | ((u32)bf16lo_us(w_k1_n8) << 16);
        L.z = (u32)bf16lo_us(w_k8_n)  | ((u32)bf16lo_us(w_k9_n)  << 16);
        L.w = (u32)bf16lo_us(w_k8_n8) | ((u32)bf16lo_us(w_k9_n8) << 16);
        g_WfragH[unit] = H;
        g_WfragL[unit] = L;
    }
}

// ================= K1: stats — block=j, 128 threads (t=graph, h=half) =================
__global__ void __launch_bounds__(128) stats_kernel(const float* __restrict__ W1,
                                                    const float* __restrict__ b1,
                                                    const float* __restrict__ gamma,
                                                    const float* __restrict__ beta){
    __shared__ float wcol[64], wb[128];
    __shared__ float uh[2][64], sgwh[2][64], csh[2][64];
    __shared__ float rs0[4], rs1[4], rs2[4];
    int j = blockIdx.x;
    int tid = threadIdx.x, t = tid & 63, h = tid >> 6;

    if (h == 0) wcol[t] = W1[t*D + j];
    wb[tid] = W1[(64 + tid)*D + j];
    __syncthreads();

    float cs = 0.0f;
    #pragma unroll 8
    for (int s = 0; s < 32; s++) cs += wcol[h*32 + s] * g_G[(h*32 + s)*64 + t];
    csh[h][t] = cs;
    float up = (h == 0) ? b1[j] : 0.0f;
    const float4* pp = (const float4*)(g_pooled + t*128 + h*64);
    #pragma unroll 8
    for (int k4 = 0; k4 < 16; k4++){
        float4 p = pp[k4];
        int kb = h*64 + k4*4;
        up += p.x*wb[kb] + p.y*wb[kb+1] + p.z*wb[kb+2] + p.w*wb[kb+3];
    }
    uh[h][t] = up;
    float sp = 0.0f;
    const float4* spt = (const float4*)(g_s + t*64 + h*32);
    #pragma unroll 4
    for (int k4 = 0; k4 < 8; k4++){
        float4 p = spt[k4];
        int kb = h*32 + k4*4;
        sp += p.x*wcol[kb] + p.y*wcol[kb+1] + p.z*wcol[kb+2] + p.w*wcol[kb+3];
    }
    sgwh[h][t] = sp;
    __syncthreads();

    float r0 = 0.0f, r1 = 0.0f, r2 = 0.0f;
    if (h == 0){
        float u   = uh[0][t] + uh[1][t];
        g_u[t*D + j] = u;
        float sgw = sgwh[0][t] + sgwh[1][t];
        float cst = csh[0][t] + csh[1][t];
        r0 = sgw + 2048.0f*u;
        r1 = 2.0f*u*sgw + 2048.0f*u*u;
        r2 = cst * wcol[t];
    }
    #pragma unroll
    for (int o = 16; o > 0; o >>= 1){
        r0 += __shfl_down_sync(0xffffffffu, r0, o);
        r1 += __shfl_down_sync(0xffffffffu, r1, o);
        r2 += __shfl_down_sync(0xffffffffu, r2, o);
    }
    int wid = tid >> 5, lane = tid & 31;
    if (lane == 0){ rs0[wid] = r0; rs1[wid] = r1; rs2[wid] = r2; }
    __syncthreads();
    if (tid == 0){
        const float invN = 1.0f / (float)NTOT;
        float mean  = (rs0[0] + rs0[1]) * invN;
        float sumsq = (rs2[0] + rs2[1]) + (rs1[0] + rs1[1]);
        float var   = sumsq * invN - mean*mean;
        float a = gamma[j] * rsqrtf(var + 1e-5f);
        g_a[j] = a;
        g_c[j] = beta[j] - mean*a;
    }
}

// ================= K2: fused main — weight-stationary MMA, packed tanh-GELU epilogue =================
__global__ void __launch_bounds__(256, 3) main_kernel(const float* __restrict__ cond,
                                                      const float* __restrict__ W2,
                                                      const float* __restrict__ b2,
                                                      float* __restrict__ out){
    uint4* sF  = (uint4*)dsm;              // [chunk8][ks4][lane32] = 16 KB
    uint4* sWH = (uint4*)(dsm + 4096);     // ks 2,3 weight frags, 16 KB
    uint4* sWL = (uint4*)(dsm + 8192);     // 16 KB
    float* sa  = dsm + 12288;              // 256
    float* sfc = sa + 256;                 // 256
    float* sw2 = sfc + 256;                // 768
    float* sprt= sw2 + 768;                // [8][64][3] = 1536

    int tid = threadIdx.x, w = tid >> 5, l = tid & 31;
    int row0 = blockIdx.x * 64;
    int g = blockIdx.x >> 5;

    // re-zero atomic accumulators for next run (stats already consumed them)
    if (blockIdx.x == 0){
        float4 z = make_float4(0,0,0,0);
        #pragma unroll
        for (int i = 0; i < 4; i++) ((float4*)g_G)[tid + i*256] = z;
    } else if (blockIdx.x == 1){
        float4 z = make_float4(0,0,0,0);
        #pragma unroll
        for (int i = 0; i < 4; i++) ((float4*)g_s)[tid + i*256] = z;
    }

    {
        float a = g_a[tid];
        sa[tid]  = a;
        sfc[tid] = fmaf(g_u[g*D + tid], a, g_c[tid]);
    }
    for (int i = tid; i < 768; i += 256) sw2[i] = W2[i];

    // ks 0,1 weight fragments -> registers
    uint4 AH[2][2], AL[2][2];
    #pragma unroll
    for (int nt2 = 0; nt2 < 2; nt2++)
        #pragma unroll
        for (int ks = 0; ks < 2; ks++){
            int idx = ((w*2 + nt2)*4 + ks)*32 + l;
            AH[nt2][ks] = g_WfragH[idx];
            AL[nt2][ks] = g_WfragL[idx];
        }
    // ks 2,3 -> smem
    #pragma unroll
    for (int i = 0; i < 4; i++){
        int u = tid + i*256;
        int lane = u & 31, ks2 = (u >> 5) & 1, ng = u >> 6;
        int src = (ng*4 + 2 + ks2)*32 + lane;
        sWH[u] = g_WfragH[src];
        sWL[u] = g_WfragL[src];
    }

    // cond B-fragments (bf16 hi/lo) -> smem
    #pragma unroll
    for (int i = 0; i < 4; i++){
        int u = tid + i*256;
        int lane = u & 31, ks = (u >> 5) & 3, chunk = u >> 7;
        int mrow = row0 + chunk*8 + (lane >> 2);
        int k0 = ks*16 + 2*(lane & 3);
        const float* cp = cond + (size_t)mrow*COND + k0;
        float2 v01 = *(const float2*)cp;
        float2 v89 = *(const float2*)(cp + 8);
        u32 bh0, bl0, bh1, bl1;
        cvt_hl(v01, bh0, bl0);
        cvt_hl(v89, bh1, bl1);
        sF[u] = make_uint4(bh0, bh1, bl0, bl1);
    }
    __syncthreads();

    // packed per-thread BN/GEMV coefficients
    u64 ca2[2], cc2[2], cw2[2][3];
    #pragma unroll
    for (int nt2 = 0; nt2 < 2; nt2++){
        int n0 = w*32 + nt2*16 + (l >> 2);
        ca2[nt2] = pk2(sa[n0], sa[n0 + 8]);
        cc2[nt2] = pk2(sfc[n0], sfc[n0 + 8]);
        #pragma unroll
        for (int j = 0; j < 3; j++)
            cw2[nt2][j] = pk2(sw2[n0*3 + j], sw2[(n0+8)*3 + j]);
    }

    #pragma unroll 1
    for (int chunk = 0; chunk < 8; chunk++){
        float acc[2][4] = {{0,0,0,0},{0,0,0,0}};
        #pragma unroll
        for (int ks = 0; ks < 4; ks++){
            uint4 f = sF[(chunk*4 + ks)*32 + l];
            #pragma unroll
            for (int nt2 = 0; nt2 < 2; nt2++){
                uint4 wh, wl;
                if (ks < 2){ wh = AH[nt2][ks]; wl = AL[nt2][ks]; }
                else {
                    int idx = ((w*2 + nt2)*2 + (ks - 2))*32 + l;
                    wh = sWH[idx]; wl = sWL[idx];
                }
                mma16816(acc[nt2], (const u32*)&wh, f.x, f.y);
                mma16816(acc[nt2], (const u32*)&wh, f.z, f.w);
                mma16816(acc[nt2], (const u32*)&wl, f.x, f.y);
            }
        }
        u64 poc[3] = {0,0,0}, pod[3] = {0,0,0};
        #pragma unroll
        for (int nt2 = 0; nt2 < 2; nt2++){
            #pragma unroll
            for (int q = 0; q < 2; q++){
                u64 v2 = pk2(acc[nt2][q], acc[nt2][q + 2]);
                u64 y2 = fma2(v2, ca2[nt2], cc2[nt2]);
                u64 g2 = gelu2t(y2);
                u64* po = q ? pod : poc;
                po[0] = fma2(g2, cw2[nt2][0], po[0]);
                po[1] = fma2(g2, cw2[nt2][1], po[1]);
                po[2] = fma2(g2, cw2[nt2][2], po[2]);
            }
        }
        float oc[3], od[3];
        #pragma unroll
        for (int j = 0; j < 3; j++){
            float2 a = upk2(poc[j]); oc[j] = a.x + a.y;
            float2 b = upk2(pod[j]); od[j] = b.x + b.y;
        }
        #pragma unroll
        for (int j = 0; j < 3; j++){
            #pragma unroll
            for (int o = 4; o < 32; o <<= 1){
                oc[j] += __shfl_xor_sync(0xffffffffu, oc[j], o);
                od[j] += __shfl_xor_sync(0xffffffffu, od[j], o);
            }
        }
        if (l < 4){
            int r0 = chunk*8 + 2*l;
            #pragma unroll
            for (int j = 0; j < 3; j++){
                sprt[(w*64 + r0    )*3 + j] = oc[j];
                sprt[(w*64 + r0 + 1)*3 + j] = od[j];
            }
        }
    }
    __syncthreads();

    if (tid < 192){
        float s = b2[tid % 3];
        #pragma unroll
        for (int wi = 0; wi < 8; wi++) s += sprt[wi*192 + tid];
        out[(size_t)row0*3 + tid] = s;
    }
}

// ================= launch =================
extern "C" void kernel_launch(void* const* d_in, const int* in_sizes, int n_in,
                              void* d_out, int out_size){
    const float* x     = (const float*)d_in[0];
    const float* cond  = (const float*)d_in[2];
    const float* W1    = (const float*)d_in[3];
    const float* b1    = (const float*)d_in[4];
    const float* gamma = (const float*)d_in[5];
    const float* beta  = (const float*)d_in[6];
    const float* W2    = (const float*)d_in[7];
    const float* b2    = (const float*)d_in[8];
    float* out = (float*)d_out;

    static int configured = 0;
    if (!configured){
        cudaFuncSetAttribute(main_kernel, cudaFuncAttributeMaxDynamicSharedMemorySize, 60416);
        configured = 1;
    }

    prep_kernel <<<1288, 256>>>(x, cond, W1);
    stats_kernel<<<256,  128>>>(W1, b1, gamma, beta);
    main_kernel <<<2048, 256, 60416>>>(cond, W2, b2, out);
}

// round 10
// speedup vs baseline: 2.1625x; 1.1296x over previous
#include <cuda_runtime.h>
#include <cuda_bf16.h>

#define NTOT (64*2048)
#define D    256
#define COND 64
#define NG   64
#define NPG  2048

typedef unsigned long long u64;
typedef unsigned int u32;

// ---------------- device scratch ----------------
__device__ float g_pooled[NG*128];
__device__ float g_u[NG*D];
__device__ float g_G[COND*COND];      // atomic-accumulated Gram (zeroed by main each run)
__device__ float g_s[NG*COND];        // atomic-accumulated per-graph col sums
__device__ float g_a[D];
__device__ float g_c[D];
__device__ uint4 g_WfragH[2048];
__device__ uint4 g_WfragL[2048];

extern __shared__ float dsm[];

// ---------------- f32x2 + misc helpers ----------------
__device__ __forceinline__ u64 fma2(u64 a, u64 b, u64 c){
    u64 d; asm("fma.rn.f32x2 %0, %1, %2, %3;" : "=l"(d) : "l"(a), "l"(b), "l"(c)); return d;
}
__device__ __forceinline__ u64 mul2(u64 a, u64 b){
    u64 d; asm("mul.rn.f32x2 %0, %1, %2;" : "=l"(d) : "l"(a), "l"(b)); return d;
}
__device__ __forceinline__ u64 add2(u64 a, u64 b){
    u64 d; asm("add.rn.f32x2 %0, %1, %2;" : "=l"(d) : "l"(a), "l"(b)); return d;
}
__device__ __forceinline__ u64 dup2(float v){
    u64 r; asm("mov.b64 %0, {%1, %1};" : "=l"(r) : "f"(v)); return r;
}
__device__ __forceinline__ u64 pk2(float x, float y){
    u64 r; asm("mov.b64 %0, {%1, %2};" : "=l"(r) : "f"(x), "f"(y)); return r;
}
__device__ __forceinline__ float2 upk2(u64 v){
    float2 f; asm("mov.b64 {%0, %1}, %2;" : "=f"(f.x), "=f"(f.y) : "l"(v)); return f;
}
__device__ __forceinline__ unsigned short bf16hi_us(float w){
    return __bfloat16_as_ushort(__float2bfloat16(w));
}
__device__ __forceinline__ unsigned short bf16lo_us(float w){
    float r = w - __bfloat162float(__float2bfloat16(w));
    return __bfloat16_as_ushort(__float2bfloat16(r));
}
__device__ __forceinline__ void cvt_hl(float2 v, u32& hi, u32& lo){
    __nv_bfloat162 h = __float22bfloat162_rn(v);
    float2 hf = __bfloat1622float2(h);
    __nv_bfloat162 l2 = __float22bfloat162_rn(make_float2(v.x - hf.x, v.y - hf.y));
    hi = *reinterpret_cast<u32*>(&h);
    lo = *reinterpret_cast<u32*>(&l2);
}
__device__ __forceinline__ void mma16816(float* c, const u32* a, u32 b0, u32 b1){
    asm("mma.sync.aligned.m16n8k16.row.col.f32.bf16.bf16.f32 "
        "{%0,%1,%2,%3}, {%4,%5,%6,%7}, {%8,%9}, {%0,%1,%2,%3};"
        : "+f"(c[0]), "+f"(c[1]), "+f"(c[2]), "+f"(c[3])
        : "r"(a[0]), "r"(a[1]), "r"(a[2]), "r"(a[3]), "r"(b0), "r"(b1));
}

// Packed tanh-form GELU using MUFU.TANH
__device__ __forceinline__ u64 gelu2t(u64 y2){
    u64 xx    = mul2(y2, y2);
    u64 inner = fma2(xx, dup2(0.044715f), dup2(1.0f));
    u64 arg   = mul2(mul2(y2, inner), dup2(0.79788456080286536f));
    float2 av = upk2(arg);
    float t0, t1;
    asm("tanh.approx.f32 %0, %1;" : "=f"(t0) : "f"(av.x));
    asm("tanh.approx.f32 %0, %1;" : "=f"(t1) : "f"(av.y));
    u64 half = fma2(pk2(t0, t1), dup2(0.5f), dup2(0.5f));
    return mul2(y2, half);
}

// ================= K0: prep — gram(0..511) + wfrag(512..519) + pool(520..1543) =================
// LPT ordering: long gram blocks launch first, pool blocks pack around them.
__global__ void __launch_bounds__(256) prep_kernel(const float* __restrict__ x,
                                                   const float* __restrict__ cond,
                                                   const float* __restrict__ W1){
    __shared__ float tile[8192];
    int blk = blockIdx.x, tid = threadIdx.x;

    if (blk < 512){
        // ---- gram: 512 blocks x 256 rows, atomic accumulate into g_G / g_s ----
        int gb = blk;
        int ti = tid >> 4, tj = tid & 15;
        int ri = ti*4, cj = tj*4;
        u64 acc[4][2];
        #pragma unroll
        for (int r = 0; r < 4; r++){ acc[r][0] = 0ull; acc[r][1] = 0ull; }
        float ssum = 0.0f;

        for (int sub = 0; sub < 2; sub++){
            size_t base = ((size_t)gb*256 + sub*128) * COND;
            for (int i = tid; i < 8192; i += 256) tile[i] = cond[base + i];
            __syncthreads();
            #pragma unroll 4
            for (int k = 0; k < 128; k++){
                float4 av = *(const float4*)(tile + k*64 + ri);
                u64 A0 = dup2(av.x), A1 = dup2(av.y), A2 = dup2(av.z), A3 = dup2(av.w);
                ulonglong2 bb = *(const ulonglong2*)(tile + k*64 + cj);
                acc[0][0] = fma2(A0, bb.x, acc[0][0]);
                acc[0][1] = fma2(A0, bb.y, acc[0][1]);
                acc[1][0] = fma2(A1, bb.x, acc[1][0]);
                acc[1][1] = fma2(A1, bb.y, acc[1][1]);
                acc[2][0] = fma2(A2, bb.x, acc[2][0]);
                acc[2][1] = fma2(A2, bb.y, acc[2][1]);
                acc[3][0] = fma2(A3, bb.x, acc[3][0]);
                acc[3][1] = fma2(A3, bb.y, acc[3][1]);
            }
            if (tid < 64){
                #pragma unroll 8
                for (int k = 0; k < 128; k++) ssum += tile[k*64 + tid];
            }
            __syncthreads();
        }
        #pragma unroll
        for (int r = 0; r < 4; r++){
            float2 v0 = upk2(acc[r][0]);
            float2 v1 = upk2(acc[r][1]);
            atomicAdd(&g_G[(ri + r)*64 + cj + 0], v0.x);
            atomicAdd(&g_G[(ri + r)*64 + cj + 1], v0.y);
            atomicAdd(&g_G[(ri + r)*64 + cj + 2], v1.x);
            atomicAdd(&g_G[(ri + r)*64 + cj + 3], v1.y);
        }
        if (tid < 64) atomicAdd(&g_s[(gb >> 3)*64 + tid], ssum);
        return;
    }
    if (blk < 520){
        // ---- wfrag: blocks 512..519 build weight A-fragments ----
        int unit = (blk - 512)*256 + tid;     // 0..2047
        int lane = unit & 31, ks = (unit >> 5) & 3, ng = unit >> 7;
        int n  = ng*16 + (lane >> 2);
        int k  = ks*16 + 2*(lane & 3);
        float w_k_n   = W1[k*D + n],        w_k1_n  = W1[(k+1)*D + n];
        float w_k_n8  = W1[k*D + n + 8],    w_k1_n8 = W1[(k+1)*D + n + 8];
        float w_k8_n  = W1[(k+8)*D + n],    w_k9_n  = W1[(k+9)*D + n];
        float w_k8_n8 = W1[(k+8)*D + n + 8],w_k9_n8 = W1[(k+9)*D + n + 8];
        uint4 H, L;
        H.x = (u32)bf16hi_us(w_k_n)   | ((u32)bf16hi_us(w_k1_n)  << 16);
        H.y = (u32)bf16hi_us(w_k_n8)  | ((u32)bf16hi_us(w_k1_n8) << 16);
        H.z = (u32)bf16hi_us(w_k8_n)  | ((u32)bf16hi_us(w_k9_n)  << 16);
        H.w = (u32)bf16hi_us(w_k8_n8) | ((u32)bf16hi_us(w_k9_n8) << 16);
        L.x = (u32)bf16lo_us(w_k_n)   | ((u32)bf16lo_us(w_k1_n)  << 16);
        L.y = (u32)bf16lo_us(w_k_n8)  | ((u32)bf16lo_us(w_k1_n8) << 16);
        L.z = (u32)bf16lo_us(w_k8_n)  | ((u32)bf16lo_us(w_k9_n)  << 16);
        L.w = (u32)bf16lo_us(w_k8_n8) | ((u32)bf16lo_us(w_k9_n8) << 16);
        g_WfragH[unit] = H;
        g_WfragL[unit] = L;
        return;
    }
    // ---- pool: blocks 520..1543 = (graph b, oh); deep LDG.128 batching ----
    {
        int pb = blk - 520;
        int b = pb >> 4, oh = pb & 15;
        int c4 = tid & 63, rg = tid >> 6;
        const ulonglong2* p = (const ulonglong2*)(x + ((size_t)(b*NPG + oh*128 + rg))*D) + c4;
        u64 s01 = 0ull, s23 = 0ull;
        #pragma unroll 16
        for (int k = 0; k < 32; k++){
            ulonglong2 v = p[(size_t)k*256];
            s01 = add2(s01, v.x);
            s23 = add2(s23, v.y);
        }
        ulonglong2* sp = (ulonglong2*)tile;
        sp[tid] = make_ulonglong2(s01, s23);
        __syncthreads();
        if (tid < 64){
            ulonglong2 a = sp[tid], b2v = sp[tid+64], c = sp[tid+128], d = sp[tid+192];
            u64 t01 = add2(add2(a.x, b2v.x), add2(c.x, d.x));
            u64 t23 = add2(add2(a.y, b2v.y), add2(c.y, d.y));
            float2 f01 = upk2(t01), f23 = upk2(t23);
            float t = (f01.x + f01.y) + (f23.x + f23.y);
            t += __shfl_down_sync(0xffffffffu, t, 4, 8);
            t += __shfl_down_sync(0xffffffffu, t, 2, 8);
            t += __shfl_down_sync(0xffffffffu, t, 1, 8);
            if ((tid & 7) == 0) g_pooled[b*128 + oh*8 + (tid >> 3)] = t * (1.0f/4096.0f);
        }
    }
}

// ================= K1: stats — block=j, 128 threads (t=graph, h=half) =================
__global__ void __launch_bounds__(128) stats_kernel(const float* __restrict__ W1,
                                                    const float* __restrict__ b1,
                                                    const float* __restrict__ gamma,
                                                    const float* __restrict__ beta){
    __shared__ float wcol[64], wb[128];
    __shared__ float uh[2][64], sgwh[2][64], csh[2][64];
    __shared__ float rs0[4], rs1[4], rs2[4];
    int j = blockIdx.x;
    int tid = threadIdx.x, t = tid & 63, h = tid >> 6;

    if (h == 0) wcol[t] = W1[t*D + j];
    wb[tid] = W1[(64 + tid)*D + j];
    __syncthreads();

    float cs = 0.0f;
    #pragma unroll 8
    for (int s = 0; s < 32; s++) cs += wcol[h*32 + s] * g_G[(h*32 + s)*64 + t];
    csh[h][t] = cs;
    float up = (h == 0) ? b1[j] : 0.0f;
    const float4* pp = (const float4*)(g_pooled + t*128 + h*64);
    #pragma unroll 8
    for (int k4 = 0; k4 < 16; k4++){
        float4 p = pp[k4];
        int kb = h*64 + k4*4;
        up += p.x*wb[kb] + p.y*wb[kb+1] + p.z*wb[kb+2] + p.w*wb[kb+3];
    }
    uh[h][t] = up;
    float sp = 0.0f;
    const float4* spt = (const float4*)(g_s + t*64 + h*32);
    #pragma unroll 4
    for (int k4 = 0; k4 < 8; k4++){
        float4 p = spt[k4];
        int kb = h*32 + k4*4;
        sp += p.x*wcol[kb] + p.y*wcol[kb+1] + p.z*wcol[kb+2] + p.w*wcol[kb+3];
    }
    sgwh[h][t] = sp;
    __syncthreads();

    float r0 = 0.0f, r1 = 0.0f, r2 = 0.0f;
    if (h == 0){
        float u   = uh[0][t] + uh[1][t];
        g_u[t*D + j] = u;
        float sgw = sgwh[0][t] + sgwh[1][t];
        float cst = csh[0][t] + csh[1][t];
        r0 = sgw + 2048.0f*u;
        r1 = 2.0f*u*sgw + 2048.0f*u*u;
        r2 = cst * wcol[t];
    }
    #pragma unroll
    for (int o = 16; o > 0; o >>= 1){
        r0 += __shfl_down_sync(0xffffffffu, r0, o);
        r1 += __shfl_down_sync(0xffffffffu, r1, o);
        r2 += __shfl_down_sync(0xffffffffu, r2, o);
    }
    int wid = tid >> 5, lane = tid & 31;
    if (lane == 0){ rs0[wid] = r0; rs1[wid] = r1; rs2[wid] = r2; }
    __syncthreads();
    if (tid == 0){
        const float invN = 1.0f / (float)NTOT;
        float mean  = (rs0[0] + rs0[1]) * invN;
        float sumsq = (rs2[0] + rs2[1]) + (rs1[0] + rs1[1]);
        float var   = sumsq * invN - mean*mean;
        float a = gamma[j] * rsqrtf(var + 1e-5f);
        g_a[j] = a;
        g_c[j] = beta[j] - mean*a;
    }
}

// ================= K2: fused main — weight-stationary MMA, packed tanh-GELU epilogue =================
__global__ void __launch_bounds__(256, 3) main_kernel(const float* __restrict__ cond,
                                                      const float* __restrict__ W2,
                                                      const float* __restrict__ b2,
                                                      float* __restrict__ out){
    uint4* sF  = (uint4*)dsm;              // [chunk8][ks4][lane32] = 16 KB
    uint4* sWH = (uint4*)(dsm + 4096);     // ks 2,3 weight frags, 16 KB
    uint4* sWL = (uint4*)(dsm + 8192);     // 16 KB
    float* sa  = dsm + 12288;              // 256
    float* sfc = sa + 256;                 // 256
    float* sw2 = sfc + 256;                // 768
    float* sprt= sw2 + 768;                // [8][64][3] = 1536

    int tid = threadIdx.x, w = tid >> 5, l = tid & 31;
    int row0 = blockIdx.x * 64;
    int g = blockIdx.x >> 5;

    // re-zero atomic accumulators for next run
    if (blockIdx.x == 0){
        float4 z = make_float4(0,0,0,0);
        #pragma unroll
        for (int i = 0; i < 4; i++) ((float4*)g_G)[tid + i*256] = z;
    } else if (blockIdx.x == 1){
        float4 z = make_float4(0,0,0,0);
        #pragma unroll
        for (int i = 0; i < 4; i++) ((float4*)g_s)[tid + i*256] = z;
    }

    {
        float a = g_a[tid];
        sa[tid]  = a;
        sfc[tid] = fmaf(g_u[g*D + tid], a, g_c[tid]);
    }
    for (int i = tid; i < 768; i += 256) sw2[i] = W2[i];

    uint4 AH[2][2], AL[2][2];
    #pragma unroll
    for (int nt2 = 0; nt2 < 2; nt2++)
        #pragma unroll
        for (int ks = 0; ks < 2; ks++){
            int idx = ((w*2 + nt2)*4 + ks)*32 + l;
            AH[nt2][ks] = g_WfragH[idx];
            AL[nt2][ks] = g_WfragL[idx];
        }
    #pragma unroll
    for (int i = 0; i < 4; i++){
        int u = tid + i*256;
        int lane = u & 31, ks2 = (u >> 5) & 1, ng = u >> 6;
        int src = (ng*4 + 2 + ks2)*32 + lane;
        sWH[u] = g_WfragH[src];
        sWL[u] = g_WfragL[src];
    }

    #pragma unroll
    for (int i = 0; i < 4; i++){
        int u = tid + i*256;
        int lane = u & 31, ks = (u >> 5) & 3, chunk = u >> 7;
        int mrow = row0 + chunk*8 + (lane >> 2);
        int k0 = ks*16 + 2*(lane & 3);
        const float* cp = cond + (size_t)mrow*COND + k0;
        float2 v01 = *(const float2*)cp;
        float2 v89 = *(const float2*)(cp + 8);
        u32 bh0, bl0, bh1, bl1;
        cvt_hl(v01, bh0, bl0);
        cvt_hl(v89, bh1, bl1);
        sF[u] = make_uint4(bh0, bh1, bl0, bl1);
    }
    __syncthreads();

    u64 ca2[2], cc2[2], cw2[2][3];
    #pragma unroll
    for (int nt2 = 0; nt2 < 2; nt2++){
        int n0 = w*32 + nt2*16 + (l >> 2);
        ca2[nt2] = pk2(sa[n0], sa[n0 + 8]);
        cc2[nt2] = pk2(sfc[n0], sfc[n0 + 8]);
        #pragma unroll
        for (int j = 0; j < 3; j++)
            cw2[nt2][j] = pk2(sw2[n0*3 + j], sw2[(n0+8)*3 + j]);
    }

    #pragma unroll 1
    for (int chunk = 0; chunk < 8; chunk++){
        float acc[2][4] = {{0,0,0,0},{0,0,0,0}};
        #pragma unroll
        for (int ks = 0; ks < 4; ks++){
            uint4 f = sF[(chunk*4 + ks)*32 + l];
            #pragma unroll
            for (int nt2 = 0; nt2 < 2; nt2++){
                uint4 wh, wl;
                if (ks < 2){ wh = AH[nt2][ks]; wl = AL[nt2][ks]; }
                else {
                    int idx = ((w*2 + nt2)*2 + (ks - 2))*32 + l;
                    wh = sWH[idx]; wl = sWL[idx];
                }
                mma16816(acc[nt2], (const u32*)&wh, f.x, f.y);
                mma16816(acc[nt2], (const u32*)&wh, f.z, f.w);
                mma16816(acc[nt2], (const u32*)&wl, f.x, f.y);
            }
        }
        u64 poc[3] = {0,0,0}, pod[3] = {0,0,0};
        #pragma unroll
        for (int nt2 = 0; nt2 < 2; nt2++){
            #pragma unroll
            for (int q = 0; q < 2; q++){
                u64 v2 = pk2(acc[nt2][q], acc[nt2][q + 2]);
                u64 y2 = fma2(v2, ca2[nt2], cc2[nt2]);
                u64 g2 = gelu2t(y2);
                u64* po = q ? pod : poc;
                po[0] = fma2(g2, cw2[nt2][0], po[0]);
                po[1] = fma2(g2, cw2[nt2][1], po[1]);
                po[2] = fma2(g2, cw2[nt2][2], po[2]);
            }
        }
        float oc[3], od[3];
        #pragma unroll
        for (int j = 0; j < 3; j++){
            float2 a = upk2(poc[j]); oc[j] = a.x + a.y;
            float2 b = upk2(pod[j]); od[j] = b.x + b.y;
        }
        #pragma unroll
        for (int j = 0; j < 3; j++){
            #pragma unroll
            for (int o = 4; o < 32; o <<= 1){
                oc[j] += __shfl_xor_sync(0xffffffffu, oc[j], o);
                od[j] += __shfl_xor_sync(0xffffffffu, od[j], o);
            }
        }
        if (l < 4){
            int r0 = chunk*8 + 2*l;
            #pragma unroll
            for (int j = 0; j < 3; j++){
                sprt[(w*64 + r0    )*3 + j] = oc[j];
                sprt[(w*64 + r0 + 1)*3 + j] = od[j];
            }
        }
    }
    __syncthreads();

    if (tid < 192){
        float s = b2[tid % 3];
        #pragma unroll
        for (int wi = 0; wi < 8; wi++) s += sprt[wi*192 + tid];
        out[(size_t)row0*3 + tid] = s;
    }
}

// ================= launch =================
extern "C" void kernel_launch(void* const* d_in, const int* in_sizes, int n_in,
                              void* d_out, int out_size){
    const float* x     = (const float*)d_in[0];
    const float* cond  = (const float*)d_in[2];
    const float* W1    = (const float*)d_in[3];
    const float* b1    = (const float*)d_in[4];
    const float* gamma = (const float*)d_in[5];
    const float* beta  = (const float*)d_in[6];
    const float* W2    = (const float*)d_in[7];
    const float* b2    = (const float*)d_in[8];
    float* out = (float*)d_out;

    static int configured = 0;
    if (!configured){
        cudaFuncSetAttribute(main_kernel, cudaFuncAttributeMaxDynamicSharedMemorySize, 60416);
        configured = 1;
    }

    prep_kernel <<<1544, 256>>>(x, cond, W1);
    stats_kernel<<<256,  128>>>(W1, b1, gamma, beta);
    main_kernel <<<2048, 256, 60416>>>(cond, W2, b2, out);
}

// round 12
// speedup vs baseline: 2.2836x; 1.0560x over previous
#include <cuda_runtime.h>
#include <cuda_bf16.h>

#define NTOT (64*2048)
#define D    256
#define COND 64
#define NG   64
#define NPG  2048

typedef unsigned long long u64;
typedef unsigned int u32;

// ---------------- device scratch ----------------
__device__ float g_pooled[NG*128];    // atomic-accumulated (zeroed by main each run)
__device__ float g_u[NG*D];
__device__ float g_G[COND*COND];      // atomic-accumulated Gram (zeroed by main each run)
__device__ float g_s[NG*COND];        // atomic-accumulated per-graph col sums
__device__ float g_a[D];
__device__ float g_c[D];
__device__ uint4 g_WfragH[2048];
__device__ uint4 g_WfragL[2048];

extern __shared__ float dsm[];

// ---------------- f32x2 + misc helpers ----------------
__device__ __forceinline__ u64 fma2(u64 a, u64 b, u64 c){
    u64 d; asm("fma.rn.f32x2 %0, %1, %2, %3;" : "=l"(d) : "l"(a), "l"(b), "l"(c)); return d;
}
__device__ __forceinline__ u64 mul2(u64 a, u64 b){
    u64 d; asm("mul.rn.f32x2 %0, %1, %2;" : "=l"(d) : "l"(a), "l"(b)); return d;
}
__device__ __forceinline__ u64 add2(u64 a, u64 b){
    u64 d; asm("add.rn.f32x2 %0, %1, %2;" : "=l"(d) : "l"(a), "l"(b)); return d;
}
__device__ __forceinline__ u64 dup2(float v){
    u64 r; asm("mov.b64 %0, {%1, %1};" : "=l"(r) : "f"(v)); return r;
}
__device__ __forceinline__ u64 pk2(float x, float y){
    u64 r; asm("mov.b64 %0, {%1, %2};" : "=l"(r) : "f"(x), "f"(y)); return r;
}
__device__ __forceinline__ float2 upk2(u64 v){
    float2 f; asm("mov.b64 {%0, %1}, %2;" : "=f"(f.x), "=f"(f.y) : "l"(v)); return f;
}
__device__ __forceinline__ unsigned short bf16hi_us(float w){
    return __bfloat16_as_ushort(__float2bfloat16(w));
}
__device__ __forceinline__ unsigned short bf16lo_us(float w){
    float r = w - __bfloat162float(__float2bfloat16(w));
    return __bfloat16_as_ushort(__float2bfloat16(r));
}
__device__ __forceinline__ void cvt_hl(float2 v, u32& hi, u32& lo){
    __nv_bfloat162 h = __float22bfloat162_rn(v);
    float2 hf = __bfloat1622float2(h);
    __nv_bfloat162 l2 = __float22bfloat162_rn(make_float2(v.x - hf.x, v.y - hf.y));
    hi = *reinterpret_cast<u32*>(&h);
    lo = *reinterpret_cast<u32*>(&l2);
}
__device__ __forceinline__ void mma16816(float* c, const u32* a, u32 b0, u32 b1){
    asm("mma.sync.aligned.m16n8k16.row.col.f32.bf16.bf16.f32 "
        "{%0,%1,%2,%3}, {%4,%5,%6,%7}, {%8,%9}, {%0,%1,%2,%3};"
        : "+f"(c[0]), "+f"(c[1]), "+f"(c[2]), "+f"(c[3])
        : "r"(a[0]), "r"(a[1]), "r"(a[2]), "r"(a[3]), "r"(b0), "r"(b1));
}

// Packed tanh-form GELU using MUFU.TANH
__device__ __forceinline__ u64 gelu2t(u64 y2){
    u64 xx    = mul2(y2, y2);
    u64 inner = fma2(xx, dup2(0.044715f), dup2(1.0f));
    u64 arg   = mul2(mul2(y2, inner), dup2(0.79788456080286536f));
    float2 av = upk2(arg);
    float t0, t1;
    asm("tanh.approx.f32 %0, %1;" : "=f"(t0) : "f"(av.x));
    asm("tanh.approx.f32 %0, %1;" : "=f"(t1) : "f"(av.y));
    u64 half = fma2(pk2(t0, t1), dup2(0.5f), dup2(0.5f));
    return mul2(y2, half);
}

// ================= K0: prep — gram(0..511) + wfrag(512..519) + pool(520..2567) =================
// 16 KB static smem -> 8 blocks/SM. LPT: long gram blocks first.
__global__ void __launch_bounds__(256) prep_kernel(const float* __restrict__ x,
                                                   const float* __restrict__ cond,
                                                   const float* __restrict__ W1){
    __shared__ float tile[4096];   // 16 KB
    int blk = blockIdx.x, tid = threadIdx.x;

    if (blk < 512){
        // ---- gram: 512 blocks x 256 rows (4 sub-tiles of 64), atomics into g_G / g_s ----
        int gb = blk;
        int ti = tid >> 4, tj = tid & 15;
        int ri = ti*4, cj = tj*4;
        u64 acc[4][2];
        #pragma unroll
        for (int r = 0; r < 4; r++){ acc[r][0] = 0ull; acc[r][1] = 0ull; }
        float ssum = 0.0f;

        for (int sub = 0; sub < 4; sub++){
            size_t base = ((size_t)gb*256 + sub*64) * COND;
            for (int i = tid; i < 4096; i += 256) tile[i] = cond[base + i];
            __syncthreads();
            #pragma unroll 4
            for (int k = 0; k < 64; k++){
                float4 av = *(const float4*)(tile + k*64 + ri);
                u64 A0 = dup2(av.x), A1 = dup2(av.y), A2 = dup2(av.z), A3 = dup2(av.w);
                ulonglong2 bb = *(const ulonglong2*)(tile + k*64 + cj);
                acc[0][0] = fma2(A0, bb.x, acc[0][0]);
                acc[0][1] = fma2(A0, bb.y, acc[0][1]);
                acc[1][0] = fma2(A1, bb.x, acc[1][0]);
                acc[1][1] = fma2(A1, bb.y, acc[1][1]);
                acc[2][0] = fma2(A2, bb.x, acc[2][0]);
                acc[2][1] = fma2(A2, bb.y, acc[2][1]);
                acc[3][0] = fma2(A3, bb.x, acc[3][0]);
                acc[3][1] = fma2(A3, bb.y, acc[3][1]);
            }
            if (tid < 64){
                #pragma unroll 8
                for (int k = 0; k < 64; k++) ssum += tile[k*64 + tid];
            }
            __syncthreads();
        }
        #pragma unroll
        for (int r = 0; r < 4; r++){
            float2 v0 = upk2(acc[r][0]);
            float2 v1 = upk2(acc[r][1]);
            atomicAdd(&g_G[(ri + r)*64 + cj + 0], v0.x);
            atomicAdd(&g_G[(ri + r)*64 + cj + 1], v0.y);
            atomicAdd(&g_G[(ri + r)*64 + cj + 2], v1.x);
            atomicAdd(&g_G[(ri + r)*64 + cj + 3], v1.y);
        }
        if (tid < 64) atomicAdd(&g_s[(gb >> 3)*64 + tid], ssum);
        return;
    }
    if (blk < 520){
        // ---- wfrag: blocks 512..519 build weight A-fragments ----
        int unit = (blk - 512)*256 + tid;     // 0..2047
        int lane = unit & 31, ks = (unit >> 5) & 3, ng = unit >> 7;
        int n  = ng*16 + (lane >> 2);
        int k  = ks*16 + 2*(lane & 3);
        float w_k_n   = W1[k*D + n],        w_k1_n  = W1[(k+1)*D + n];
        float w_k_n8  = W1[k*D + n + 8],    w_k1_n8 = W1[(k+1)*D + n + 8];
        float w_k8_n  = W1[(k+8)*D + n],    w_k9_n  = W1[(k+9)*D + n];
        float w_k8_n8 = W1[(k+8)*D + n + 8],w_k9_n8 = W1[(k+9)*D + n + 8];
        uint4 H, L;
        H.x = (u32)bf16hi_us(w_k_n)   | ((u32)bf16hi_us(w_k1_n)  << 16);
        H.y = (u32)bf16hi_us(w_k_n8)  | ((u32)bf16hi_us(w_k1_n8) << 16);
        H.z = (u32)bf16hi_us(w_k8_n)  | ((u32)bf16hi_us(w_k9_n)  << 16);
        H.w = (u32)bf16hi_us(w_k8_n8) | ((u32)bf16hi_us(w_k9_n8) << 16);
        L.x = (u32)bf16lo_us(w_k_n)   | ((u32)bf16lo_us(w_k1_n)  << 16);
        L.y = (u32)bf16lo_us(w_k_n8)  | ((u32)bf16lo_us(w_k1_n8) << 16);
        L.z = (u32)bf16lo_us(w_k8_n)  | ((u32)bf16lo_us(w_k9_n)  << 16);
        L.w = (u32)bf16lo_us(w_k8_n8) | ((u32)bf16lo_us(w_k9_n8) << 16);
        g_WfragH[unit] = H;
        g_WfragL[unit] = L;
        return;
    }
    // ---- pool: blocks 520..2567; 64 rows each, atomic partial sums ----
    {
        int pb = blk - 520;                   // 0..2047
        int b = pb >> 5, sub = pb & 31;       // rows [sub*64, sub*64+64)
        int c4 = tid & 63, rg = tid >> 6;
        const ulonglong2* p = (const ulonglong2*)(x + ((size_t)(b*NPG + sub*64 + rg))*D) + c4;
        u64 s01 = 0ull, s23 = 0ull;
        #pragma unroll 16
        for (int k = 0; k < 16; k++){
            ulonglong2 v = p[(size_t)k*256];  // stride 4 rows
            s01 = add2(s01, v.x);
            s23 = add2(s23, v.y);
        }
        ulonglong2* sp = (ulonglong2*)tile;
        sp[tid] = make_ulonglong2(s01, s23);
        __syncthreads();
        if (tid < 64){
            ulonglong2 a = sp[tid], b2v = sp[tid+64], c = sp[tid+128], d = sp[tid+192];
            u64 t01 = add2(add2(a.x, b2v.x), add2(c.x, d.x));
            u64 t23 = add2(add2(a.y, b2v.y), add2(c.y, d.y));
            float2 f01 = upk2(t01), f23 = upk2(t23);
            float t = (f01.x + f01.y) + (f23.x + f23.y);
            t += __shfl_down_sync(0xffffffffu, t, 4, 8);
            t += __shfl_down_sync(0xffffffffu, t, 2, 8);
            t += __shfl_down_sync(0xffffffffu, t, 1, 8);
            if ((tid & 7) == 0)
                atomicAdd(&g_pooled[b*128 + (sub >> 1)*8 + (tid >> 3)], t * (1.0f/4096.0f));
        }
    }
}

// ================= K1: stats — block=j, 128 threads (t=graph, h=half) =================
__global__ void __launch_bounds__(128) stats_kernel(const float* __restrict__ W1,
                                                    const float* __restrict__ b1,
                                                    const float* __restrict__ gamma,
                                                    const float* __restrict__ beta){
    __shared__ float wcol[64], wb[128];
    __shared__ float uh[2][64], sgwh[2][64], csh[2][64];
    __shared__ float rs0[4], rs1[4], rs2[4];
    int j = blockIdx.x;
    int tid = threadIdx.x, t = tid & 63, h = tid >> 6;

    if (h == 0) wcol[t] = W1[t*D + j];
    wb[tid] = W1[(64 + tid)*D + j];
    __syncthreads();

    float cs = 0.0f;
    #pragma unroll 8
    for (int s = 0; s < 32; s++) cs += wcol[h*32 + s] * g_G[(h*32 + s)*64 + t];
    csh[h][t] = cs;
    float up = (h == 0) ? b1[j] : 0.0f;
    const float4* pp = (const float4*)(g_pooled + t*128 + h*64);
    #pragma unroll 8
    for (int k4 = 0; k4 < 16; k4++){
        float4 p = pp[k4];
        int kb = h*64 + k4*4;
        up += p.x*wb[kb] + p.y*wb[kb+1] + p.z*wb[kb+2] + p.w*wb[kb+3];
    }
    uh[h][t] = up;
    float sp = 0.0f;
    const float4* spt = (const float4*)(g_s + t*64 + h*32);
    #pragma unroll 4
    for (int k4 = 0; k4 < 8; k4++){
        float4 p = spt[k4];
        int kb = h*32 + k4*4;
        sp += p.x*wcol[kb] + p.y*wcol[kb+1] + p.z*wcol[kb+2] + p.w*wcol[kb+3];
    }
    sgwh[h][t] = sp;
    __syncthreads();

    float r0 = 0.0f, r1 = 0.0f, r2 = 0.0f;
    if (h == 0){
        float u   = uh[0][t] + uh[1][t];
        g_u[t*D + j] = u;
        float sgw = sgwh[0][t] + sgwh[1][t];
        float cst = csh[0][t] + csh[1][t];
        r0 = sgw + 2048.0f*u;
        r1 = 2.0f*u*sgw + 2048.0f*u*u;
        r2 = cst * wcol[t];
    }
    #pragma unroll
    for (int o = 16; o > 0; o >>= 1){
        r0 += __shfl_down_sync(0xffffffffu, r0, o);
        r1 += __shfl_down_sync(0xffffffffu, r1, o);
        r2 += __shfl_down_sync(0xffffffffu, r2, o);
    }
    int wid = tid >> 5, lane = tid & 31;
    if (lane == 0){ rs0[wid] = r0; rs1[wid] = r1; rs2[wid] = r2; }
    __syncthreads();
    if (tid == 0){
        const float invN = 1.0f / (float)NTOT;
        float mean  = (rs0[0] + rs0[1]) * invN;
        float sumsq = (rs2[0] + rs2[1]) + (rs1[0] + rs1[1]);
        float var   = sumsq * invN - mean*mean;
        float a = gamma[j] * rsqrtf(var + 1e-5f);
        g_a[j] = a;
        g_c[j] = beta[j] - mean*a;
    }
}

// ================= K2: fused main — weight-stationary MMA, packed tanh-GELU epilogue =================
__global__ void __launch_bounds__(256, 3) main_kernel(const float* __restrict__ cond,
                                                      const float* __restrict__ W2,
                                                      const float* __restrict__ b2,
                                                      float* __restrict__ out){
    uint4* sF  = (uint4*)dsm;              // [chunk8][ks4][lane32] = 16 KB
    uint4* sWH = (uint4*)(dsm + 4096);     // ks 2,3 weight frags, 16 KB
    uint4* sWL = (uint4*)(dsm + 8192);     // 16 KB
    float* sa  = dsm + 12288;              // 256
    float* sfc = sa + 256;                 // 256
    float* sw2 = sfc + 256;                // 768
    float* sprt= sw2 + 768;                // [8][64][3] = 1536

    int tid = threadIdx.x, w = tid >> 5, l = tid & 31;
    int row0 = blockIdx.x * 64;
    int g = blockIdx.x >> 5;

    // re-zero atomic accumulators for next replay
    // g_G: 1024 float4, g_s: 1024 float4, g_pooled: 2048 float4
    if (blockIdx.x == 0){
        float4 z = make_float4(0,0,0,0);
        #pragma unroll
        for (int i = 0; i < 4; i++) ((float4*)g_G)[tid + i*256] = z;
    } else if (blockIdx.x == 1){
        float4 z = make_float4(0,0,0,0);
        #pragma unroll
        for (int i = 0; i < 4; i++) ((float4*)g_s)[tid + i*256] = z;
    } else if (blockIdx.x == 2){
        float4 z = make_float4(0,0,0,0);
        #pragma unroll
        for (int i = 0; i < 4; i++) ((float4*)g_pooled)[tid + i*256] = z;
    } else if (blockIdx.x == 3){
        float4 z = make_float4(0,0,0,0);
        #pragma unroll
        for (int i = 0; i < 4; i++) ((float4*)g_pooled)[1024 + tid + i*256] = z;
    }

    {
        float a = g_a[tid];
        sa[tid]  = a;
        sfc[tid] = fmaf(g_u[g*D + tid], a, g_c[tid]);
    }
    for (int i = tid; i < 768; i += 256) sw2[i] = W2[i];

    uint4 AH[2][2], AL[2][2];
    #pragma unroll
    for (int nt2 = 0; nt2 < 2; nt2++)
        #pragma unroll
        for (int ks = 0; ks < 2; ks++){
            int idx = ((w*2 + nt2)*4 + ks)*32 + l;
            AH[nt2][ks] = g_WfragH[idx];
            AL[nt2][ks] = g_WfragL[idx];
        }
    #pragma unroll
    for (int i = 0; i < 4; i++){
        int u = tid + i*256;
        int lane = u & 31, ks2 = (u >> 5) & 1, ng = u >> 6;
        int src = (ng*4 + 2 + ks2)*32 + lane;
        sWH[u] = g_WfragH[src];
        sWL[u] = g_WfragL[src];
    }

    #pragma unroll
    for (int i = 0; i < 4; i++){
        int u = tid + i*256;
        int lane = u & 31, ks = (u >> 5) & 3, chunk = u >> 7;
        int mrow = row0 + chunk*8 + (lane >> 2);
        int k0 = ks*16 + 2*(lane & 3);
        const float* cp = cond + (size_t)mrow*COND + k0;
        float2 v01 = *(const float2*)cp;
        float2 v89 = *(const float2*)(cp + 8);
        u32 bh0, bl0, bh1, bl1;
        cvt_hl(v01, bh0, bl0);
        cvt_hl(v89, bh1, bl1);
        sF[u] = make_uint4(bh0, bh1, bl0, bl1);
    }
    __syncthreads();

    u64 ca2[2], cc2[2], cw2[2][3];
    #pragma unroll
    for (int nt2 = 0; nt2 < 2; nt2++){
        int n0 = w*32 + nt2*16 + (l >> 2);
        ca2[nt2] = pk2(sa[n0], sa[n0 + 8]);
        cc2[nt2] = pk2(sfc[n0], sfc[n0 + 8]);
        #pragma unroll
        for (int j = 0; j < 3; j++)
            cw2[nt2][j] = pk2(sw2[n0*3 + j], sw2[(n0+8)*3 + j]);
    }

    #pragma unroll 1
    for (int chunk = 0; chunk < 8; chunk++){
        float acc[2][4] = {{0,0,0,0},{0,0,0,0}};
        #pragma unroll
        for (int ks = 0; ks < 4; ks++){
            uint4 f = sF[(chunk*4 + ks)*32 + l];
            #pragma unroll
            for (int nt2 = 0; nt2 < 2; nt2++){
                uint4 wh, wl;
                if (ks < 2){ wh = AH[nt2][ks]; wl = AL[nt2][ks]; }
                else {
                    int idx = ((w*2 + nt2)*2 + (ks - 2))*32 + l;
                    wh = sWH[idx]; wl = sWL[idx];
                }
                mma16816(acc[nt2], (const u32*)&wh, f.x, f.y);
                mma16816(acc[nt2], (const u32*)&wh, f.z, f.w);
                mma16816(acc[nt2], (const u32*)&wl, f.x, f.y);
            }
        }
        u64 poc[3] = {0,0,0}, pod[3] = {0,0,0};
        #pragma unroll
        for (int nt2 = 0; nt2 < 2; nt2++){
            #pragma unroll
            for (int q = 0; q < 2; q++){
                u64 v2 = pk2(acc[nt2][q], acc[nt2][q + 2]);
                u64 y2 = fma2(v2, ca2[nt2], cc2[nt2]);
                u64 g2 = gelu2t(y2);
                u64* po = q ? pod : poc;
                po[0] = fma2(g2, cw2[nt2][0], po[0]);
                po[1] = fma2(g2, cw2[nt2][1], po[1]);
                po[2] = fma2(g2, cw2[nt2][2], po[2]);
            }
        }
        float oc[3], od[3];
        #pragma unroll
        for (int j = 0; j < 3; j++){
            float2 a = upk2(poc[j]); oc[j] = a.x + a.y;
            float2 b = upk2(pod[j]); od[j] = b.x + b.y;
        }
        #pragma unroll
        for (int j = 0; j < 3; j++){
            #pragma unroll
            for (int o = 4; o < 32; o <<= 1){
                oc[j] += __shfl_xor_sync(0xffffffffu, oc[j], o);
                od[j] += __shfl_xor_sync(0xffffffffu, od[j], o);
            }
        }
        if (l < 4){
            int r0 = chunk*8 + 2*l;
            #pragma unroll
            for (int j = 0; j < 3; j++){
                sprt[(w*64 + r0    )*3 + j] = oc[j];
                sprt[(w*64 + r0 + 1)*3 + j] = od[j];
            }
        }
    }
    __syncthreads();

    if (tid < 192){
        float s = b2[tid % 3];
        #pragma unroll
        for (int wi = 0; wi < 8; wi++) s += sprt[wi*192 + tid];
        out[(size_t)row0*3 + tid] = s;
    }
}

// ================= launch =================
extern "C" void kernel_launch(void* const* d_in, const int* in_sizes, int n_in,
                              void* d_out, int out_size){
    const float* x     = (const float*)d_in[0];
    const float* cond  = (const float*)d_in[2];
    const float* W1    = (const float*)d_in[3];
    const float* b1    = (const float*)d_in[4];
    const float* gamma = (const float*)d_in[5];
    const float* beta  = (const float*)d_in[6];
    const float* W2    = (const float*)d_in[7];
    const float* b2    = (const float*)d_in[8];
    float* out = (float*)d_out;

    static int configured = 0;
    if (!configured){
        cudaFuncSetAttribute(main_kernel, cudaFuncAttributeMaxDynamicSharedMemorySize, 60416);
        configured = 1;
    }

    prep_kernel <<<2568, 256>>>(x, cond, W1);
    stats_kernel<<<256,  128>>>(W1, b1, gamma, beta);
    main_kernel <<<2048, 256, 60416>>>(cond, W2, b2, out);
}